// round 10
// baseline (speedup 1.0000x reference)
#include <cuda_runtime.h>
#include <math.h>
#include <stdint.h>

#define B_  4
#define T_  2048
#define E_  128
#define H_  8
#define BH_ 32
#define M_  8192      // B*T
#define EH_ 1024      // E*H

// total softmax scale: e^-0.5 (folded into Q)
#define S2_ 0.08838834764831845f

// Projection GEMM smem (floats)
#define GA_STR 36
#define GB_STR 136
#define G_AS_FLOATS (128 * GA_STR)
#define G_BS_FLOATS (32 * GB_STR)
#define SMEM_GEMM ((G_AS_FLOATS + G_BS_FLOATS) * 4)     // qkv kernel

#define G_AS2_FLOATS (64 * GA_STR)
#define SMEM_OUT ((G_AS2_FLOATS + G_BS_FLOATS) * 4)     // out kernel (M-tile 64)

// Attention smem: KV stages + P (tf32 bits) + flag
#define AK_STR 132
#define AV_STR 132
#define AP_STR 68
#define ST_U32 (64 * AK_STR)                 // one K or V stage
#define SMEM_ATTN ((4 * ST_U32 + 128 * AP_STR + 4) * 4)  // ~170KB

// Scratch (device globals: allowed; runtime alloc is not)
__device__ float Qg[(size_t)BH_ * T_ * E_];   // [bh][t][e]
__device__ float Kg[(size_t)BH_ * T_ * E_];   // [bh][t][e]
__device__ float Vg[(size_t)BH_ * T_ * E_];   // [bh][t][e]
__device__ float Og[(size_t)M_ * EH_];        // [b*t][h*e]

// ---------------------------------------------------------------------------
// helpers (sm_80+ only; toolchain compiles at compute_100 non-a)
// ---------------------------------------------------------------------------
__device__ __forceinline__ uint32_t f2tf32(float f) {
    uint32_t r;
    asm("cvt.rna.tf32.f32 %0, %1;" : "=r"(r) : "f"(f));
    return r;
}
__device__ __forceinline__ void mma_tf32(float* d, const uint32_t* a, const uint32_t* b) {
    asm volatile(
        "mma.sync.aligned.m16n8k8.row.col.f32.tf32.tf32.f32 "
        "{%0,%1,%2,%3}, {%4,%5,%6,%7}, {%8,%9}, {%0,%1,%2,%3};"
        : "+f"(d[0]), "+f"(d[1]), "+f"(d[2]), "+f"(d[3])
        : "r"(a[0]), "r"(a[1]), "r"(a[2]), "r"(a[3]), "r"(b[0]), "r"(b[1]));
}
__device__ __forceinline__ uint32_t smem_u32addr(const void* p) {
    uint32_t a;
    asm("{ .reg .u64 t; cvta.to.shared.u64 t, %1; cvt.u32.u64 %0, t; }"
        : "=r"(a) : "l"(p));
    return a;
}
__device__ __forceinline__ void cpa16(uint32_t s, const void* g) {
    asm volatile("cp.async.cg.shared.global [%0], [%1], 16;" :: "r"(s), "l"(g));
}
#define CPA_COMMIT() asm volatile("cp.async.commit_group;" ::: "memory")
#define CPA_WAIT1()  asm volatile("cp.async.wait_group 1;" ::: "memory")
#define CPA_WAIT0()  asm volatile("cp.async.wait_group 0;" ::: "memory")

// ---------------------------------------------------------------------------
// Kernel 1: QKV projection via tf32 mma.sync.
// ---------------------------------------------------------------------------
__global__ __launch_bounds__(256) void qkv_mma_kernel(
    const float* __restrict__ x,
    const float* __restrict__ Wq,
    const float* __restrict__ Wk,
    const float* __restrict__ Wv)
{
    extern __shared__ float sm[];
    uint32_t* AsU = (uint32_t*)sm;
    uint32_t* BsU = (uint32_t*)(sm + G_AS_FLOATS);

    const int z  = blockIdx.z;
    const float* __restrict__ Wp = (z == 0) ? Wq : (z == 1) ? Wk : Wv;
    float* __restrict__ outp     = (z == 0) ? Qg : (z == 1) ? Kg : Vg;
    const int m0 = blockIdx.x * 128;
    const int h  = blockIdx.y;
    const int n0 = h * 128;

    const int tid  = threadIdx.x;
    const int warp = tid >> 5, lane = tid & 31;
    const int g = lane >> 2, tg = lane & 3;
    const int wm0 = (warp & 1) * 64;
    const int wn0 = (warp >> 1) * 32;

    float acc[4][4][4];
#pragma unroll
    for (int mi = 0; mi < 4; mi++)
#pragma unroll
        for (int ni = 0; ni < 4; ni++)
#pragma unroll
            for (int c = 0; c < 4; c++) acc[mi][ni][c] = 0.f;

    for (int kc = 0; kc < 4; kc++) {
        const int k0 = kc * 32;
#pragma unroll
        for (int i = 0; i < 4; i++) {
            int f = tid + i * 256;
            int row = f >> 3, s4 = f & 7;
            float4 v = *(const float4*)&x[(size_t)(m0 + row) * E_ + k0 + 4 * s4];
            AsU[row * GA_STR + 4 * s4 + 0] = f2tf32(v.x);
            AsU[row * GA_STR + 4 * s4 + 1] = f2tf32(v.y);
            AsU[row * GA_STR + 4 * s4 + 2] = f2tf32(v.z);
            AsU[row * GA_STR + 4 * s4 + 3] = f2tf32(v.w);
        }
#pragma unroll
        for (int i = 0; i < 4; i++) {
            int f = tid + i * 256;
            int kk = f >> 5, n4 = f & 31;
            float4 v = *(const float4*)&Wp[(size_t)(k0 + kk) * EH_ + n0 + 4 * n4];
            BsU[kk * GB_STR + 4 * n4 + 0] = f2tf32(v.x);
            BsU[kk * GB_STR + 4 * n4 + 1] = f2tf32(v.y);
            BsU[kk * GB_STR + 4 * n4 + 2] = f2tf32(v.z);
            BsU[kk * GB_STR + 4 * n4 + 3] = f2tf32(v.w);
        }
        __syncthreads();

#pragma unroll
        for (int ks = 0; ks < 4; ks++) {
            const int kb = 8 * ks;
            uint32_t a[4][4], b[4][2];
#pragma unroll
            for (int mi = 0; mi < 4; mi++) {
                int r = wm0 + 16 * mi + g;
                a[mi][0] = AsU[r * GA_STR + kb + tg];
                a[mi][1] = AsU[(r + 8) * GA_STR + kb + tg];
                a[mi][2] = AsU[r * GA_STR + kb + tg + 4];
                a[mi][3] = AsU[(r + 8) * GA_STR + kb + tg + 4];
            }
#pragma unroll
            for (int ni = 0; ni < 4; ni++) {
                int col = wn0 + 8 * ni + g;
                b[ni][0] = BsU[(kb + tg) * GB_STR + col];
                b[ni][1] = BsU[(kb + tg + 4) * GB_STR + col];
            }
#pragma unroll
            for (int mi = 0; mi < 4; mi++)
#pragma unroll
                for (int ni = 0; ni < 4; ni++)
                    mma_tf32(acc[mi][ni], a[mi], b[ni]);
        }
        __syncthreads();
    }

    const int b_ = m0 >> 11;
    const int t0 = m0 & 2047;
#pragma unroll
    for (int mi = 0; mi < 4; mi++) {
        int rl = wm0 + 16 * mi + g;
        size_t rbase = ((size_t)(b_ * H_ + h) * T_ + t0 + rl) * E_;
#pragma unroll
        for (int ni = 0; ni < 4; ni++) {
            int n = wn0 + 8 * ni + 2 * tg;
            *(float2*)&outp[rbase + n] =
                make_float2(acc[mi][ni][0], acc[mi][ni][1]);
            *(float2*)&outp[rbase + 8 * E_ + n] =
                make_float2(acc[mi][ni][2], acc[mi][ni][3]);
        }
    }
}

// ---------------------------------------------------------------------------
// Kernel 3: output projection, M-tile 64 -> 128 CTAs.
// ---------------------------------------------------------------------------
__global__ __launch_bounds__(256) void out_mma_kernel(
    const float* __restrict__ Wu,
    const float* __restrict__ bu,
    float* __restrict__ out)
{
    extern __shared__ float sm[];
    uint32_t* AsU = (uint32_t*)sm;                   // [64][36]
    uint32_t* BsU = (uint32_t*)(sm + G_AS2_FLOATS);  // [32][136]

    const int m0 = blockIdx.x * 64;
    const int tid  = threadIdx.x;
    const int warp = tid >> 5, lane = tid & 31;
    const int g = lane >> 2, tg = lane & 3;
    const int wm0 = (warp & 1) * 32;
    const int wn0 = (warp >> 1) * 32;

    float acc[2][4][4];
#pragma unroll
    for (int mi = 0; mi < 2; mi++)
#pragma unroll
        for (int ni = 0; ni < 4; ni++)
#pragma unroll
            for (int c = 0; c < 4; c++) acc[mi][ni][c] = 0.f;

    for (int kc = 0; kc < 32; kc++) {
        const int k0 = kc * 32;
#pragma unroll
        for (int i = 0; i < 2; i++) {
            int f = tid + i * 256;
            int row = f >> 3, s4 = f & 7;
            float4 v = *(const float4*)&Og[(size_t)(m0 + row) * EH_ + k0 + 4 * s4];
            AsU[row * GA_STR + 4 * s4 + 0] = f2tf32(v.x);
            AsU[row * GA_STR + 4 * s4 + 1] = f2tf32(v.y);
            AsU[row * GA_STR + 4 * s4 + 2] = f2tf32(v.z);
            AsU[row * GA_STR + 4 * s4 + 3] = f2tf32(v.w);
        }
#pragma unroll
        for (int i = 0; i < 4; i++) {
            int f = tid + i * 256;
            int kk = f >> 5, n4 = f & 31;
            float4 v = *(const float4*)&Wu[(size_t)(k0 + kk) * E_ + 4 * n4];
            BsU[kk * GB_STR + 4 * n4 + 0] = f2tf32(v.x);
            BsU[kk * GB_STR + 4 * n4 + 1] = f2tf32(v.y);
            BsU[kk * GB_STR + 4 * n4 + 2] = f2tf32(v.z);
            BsU[kk * GB_STR + 4 * n4 + 3] = f2tf32(v.w);
        }
        __syncthreads();

#pragma unroll
        for (int ks = 0; ks < 4; ks++) {
            const int kb = 8 * ks;
            uint32_t a[2][4], b[4][2];
#pragma unroll
            for (int mi = 0; mi < 2; mi++) {
                int r = wm0 + 16 * mi + g;
                a[mi][0] = AsU[r * GA_STR + kb + tg];
                a[mi][1] = AsU[(r + 8) * GA_STR + kb + tg];
                a[mi][2] = AsU[r * GA_STR + kb + tg + 4];
                a[mi][3] = AsU[(r + 8) * GA_STR + kb + tg + 4];
            }
#pragma unroll
            for (int ni = 0; ni < 4; ni++) {
                int col = wn0 + 8 * ni + g;
                b[ni][0] = BsU[(kb + tg) * GB_STR + col];
                b[ni][1] = BsU[(kb + tg + 4) * GB_STR + col];
            }
#pragma unroll
            for (int mi = 0; mi < 2; mi++)
#pragma unroll
                for (int ni = 0; ni < 4; ni++)
                    mma_tf32(acc[mi][ni], a[mi], b[ni]);
        }
        __syncthreads();
    }

#pragma unroll
    for (int mi = 0; mi < 2; mi++) {
        int m = m0 + wm0 + 16 * mi + g;
#pragma unroll
        for (int ni = 0; ni < 4; ni++) {
            int n = wn0 + 8 * ni + 2 * tg;
            float2 bias = *(const float2*)&bu[n];
            *(float2*)&out[(size_t)m * E_ + n] =
                make_float2(acc[mi][ni][0] + bias.x, acc[mi][ni][1] + bias.y);
            *(float2*)&out[(size_t)(m + 8) * E_ + n] =
                make_float2(acc[mi][ni][2] + bias.x, acc[mi][ni][3] + bias.y);
        }
    }
}

// ---------------------------------------------------------------------------
// Attention softmax + PV. Smem K/V already tf32-converted (cooperatively).
// ---------------------------------------------------------------------------
__device__ __forceinline__ void attn_softmax_pv(
    float sacc[8][4], float& m1, float& m2, float& l1, float& l2,
    float o[16][4], uint32_t* Ps, const uint32_t* Vs, int r1, int g, int tg)
{
    float mt1 = -INFINITY, mt2 = -INFINITY;
#pragma unroll
    for (int ni = 0; ni < 8; ni++) {
        mt1 = fmaxf(mt1, fmaxf(sacc[ni][0], sacc[ni][1]));
        mt2 = fmaxf(mt2, fmaxf(sacc[ni][2], sacc[ni][3]));
    }
    mt1 = fmaxf(mt1, __shfl_xor_sync(0xffffffffu, mt1, 1));
    mt1 = fmaxf(mt1, __shfl_xor_sync(0xffffffffu, mt1, 2));
    mt2 = fmaxf(mt2, __shfl_xor_sync(0xffffffffu, mt2, 1));
    mt2 = fmaxf(mt2, __shfl_xor_sync(0xffffffffu, mt2, 2));
    float mn1 = fmaxf(m1, mt1), mn2 = fmaxf(m2, mt2);
    float al1 = (m1 == mn1) ? 1.f : __expf(m1 - mn1);
    float al2 = (m2 == mn2) ? 1.f : __expf(m2 - mn2);
    float me1 = (mn1 == -INFINITY) ? 0.f : mn1;
    float me2 = (mn2 == -INFINITY) ? 0.f : mn2;
    float ls1 = 0.f, ls2 = 0.f;
#pragma unroll
    for (int ni = 0; ni < 8; ni++) {
        float p0 = __expf(sacc[ni][0] - me1);
        float p1 = __expf(sacc[ni][1] - me1);
        float p2 = __expf(sacc[ni][2] - me2);
        float p3 = __expf(sacc[ni][3] - me2);
        ls1 += p0 + p1; ls2 += p2 + p3;
        uint32_t* pb = Ps + r1 * AP_STR + 8 * ni + 2 * tg;
        pb[0] = f2tf32(p0); pb[1] = f2tf32(p1);
        pb[8 * AP_STR] = f2tf32(p2); pb[8 * AP_STR + 1] = f2tf32(p3);
    }
    ls1 += __shfl_xor_sync(0xffffffffu, ls1, 1);
    ls1 += __shfl_xor_sync(0xffffffffu, ls1, 2);
    ls2 += __shfl_xor_sync(0xffffffffu, ls2, 1);
    ls2 += __shfl_xor_sync(0xffffffffu, ls2, 2);
    l1 = l1 * al1 + ls1; m1 = mn1;
    l2 = l2 * al2 + ls2; m2 = mn2;
#pragma unroll
    for (int ni = 0; ni < 16; ni++) {
        o[ni][0] *= al1; o[ni][1] *= al1;
        o[ni][2] *= al2; o[ni][3] *= al2;
    }
    __syncwarp();
#pragma unroll
    for (int kp = 0; kp < 8; kp++) {
        uint32_t a[4];
        const uint32_t* pb = Ps + r1 * AP_STR + 8 * kp;
        a[0] = pb[tg]; a[1] = pb[8 * AP_STR + tg];
        a[2] = pb[tg + 4]; a[3] = pb[8 * AP_STR + tg + 4];
#pragma unroll
        for (int ni = 0; ni < 16; ni++) {
            const uint32_t* vb = Vs + (8 * kp + tg) * AV_STR + 8 * ni + g;
            uint32_t b[2] = { vb[0], vb[4 * AV_STR] };
            mma_tf32(o[ni], a, b);
        }
    }
    __syncwarp();   // all lanes done reading Ps before next tile overwrites
}

// Cooperative in-place fp32 -> tf32 conversion of one 64x128 tile (stride 132)
__device__ __forceinline__ void convert_tile_tf32(uint32_t* base, int tid)
{
#pragma unroll
    for (int i = 0; i < 8; i++) {
        int f = tid + i * 256;              // 0..2047 float4 slots
        int row = f >> 5, c4 = f & 31;
        uint32_t* p = base + row * AK_STR + 4 * c4;
        float4 v = *(const float4*)p;
        p[0] = f2tf32(v.x); p[1] = f2tf32(v.y);
        p[2] = f2tf32(v.z); p[3] = f2tf32(v.w);
    }
}

// ---------------------------------------------------------------------------
// Kernel 2: flash attention, cp.async double-buffered K/V, Q in registers,
// cooperative tf32 conversion once per tile per CTA.
// ---------------------------------------------------------------------------
__global__ __launch_bounds__(256, 1) void attn_kernel(const int* __restrict__ mask)
{
    extern __shared__ uint32_t smu[];
    uint32_t* KV = smu;                       // [K0 | V0 | K1 | V1], each ST_U32
    uint32_t* Ps = smu + 4 * ST_U32;          // [128][68]
    int* needb = (int*)(Ps + 128 * AP_STR);

    const int bh = blockIdx.y;
    const int qt = (gridDim.x - 1) - blockIdx.x;   // heavy blocks first
    const int q0 = qt * 128;
    const int tid = threadIdx.x;
    const int w = tid >> 5, lane = tid & 31;
    const int g = lane >> 2, tg = lane & 3;
    const int r1 = 16 * w + g;
    const int gq1 = q0 + r1, gq2 = gq1 + 8;

    const float* __restrict__ Qp = Qg + (size_t)bh * T_ * E_;
    const float* __restrict__ Kp = Kg + (size_t)bh * T_ * E_;
    const float* __restrict__ Vp = Vg + (size_t)bh * T_ * E_;

    const uint32_t kv_base = smem_u32addr(KV);

    // --- stage Q through KV area, convert, pull frags to regs
    {
        uint32_t* QT = KV;
#pragma unroll
        for (int i = 0; i < 16; i++) {
            int f = tid + i * 256;
            int row = f >> 5, c4 = f & 31;
            float4 v = *(const float4*)&Qp[(size_t)(q0 + row) * E_ + 4 * c4];
            uint32_t* d = QT + row * AK_STR + 4 * c4;
            d[0] = f2tf32(v.x * S2_); d[1] = f2tf32(v.y * S2_);
            d[2] = f2tf32(v.z * S2_); d[3] = f2tf32(v.w * S2_);
        }
        __syncthreads();
    }
    uint32_t qf[16][4];
#pragma unroll
    for (int ks = 0; ks < 16; ks++) {
        const uint32_t* qb = KV + r1 * AK_STR + 8 * ks;
        qf[ks][0] = qb[tg];
        qf[ks][1] = qb[8 * AK_STR + tg];
        qf[ks][2] = qb[tg + 4];
        qf[ks][3] = qb[8 * AK_STR + tg + 4];
    }
    __syncthreads();   // done reading staging area before cp.async overwrites

    float o[16][4];
#pragma unroll
    for (int ni = 0; ni < 16; ni++)
#pragma unroll
        for (int c = 0; c < 4; c++) o[ni][c] = 0.f;

    float m1 = -INFINITY, m2 = -INFINITY, l1 = 0.f, l2 = 0.f;
    const int ntA = 2 * qt + 2;

    // prefetch tile 0 into stage 0
    {
        uint32_t kb = kv_base;
        uint32_t vb = kv_base + ST_U32 * 4;
#pragma unroll
        for (int i = 0; i < 8; i++) {
            int f = tid + i * 256;
            int row = f >> 5, c4 = f & 31;
            uint32_t off = (uint32_t)(row * AK_STR + 4 * c4) * 4;
            cpa16(kb + off, Kp + (size_t)row * E_ + 4 * c4);
            cpa16(vb + off, Vp + (size_t)row * E_ + 4 * c4);
        }
        CPA_COMMIT();
    }

    for (int kt = 0; kt < ntA; kt++) {
        const int s = kt & 1;
        const int kt0 = kt * 64;

        // issue loads for kt+1 into stage s^1
        if (kt + 1 < ntA) {
            const int nk0 = (kt + 1) * 64;
            uint32_t kb = kv_base + (uint32_t)(s ^ 1) * 2 * ST_U32 * 4;
            uint32_t vb = kb + ST_U32 * 4;
#pragma unroll
            for (int i = 0; i < 8; i++) {
                int f = tid + i * 256;
                int row = f >> 5, c4 = f & 31;
                uint32_t off = (uint32_t)(row * AK_STR + 4 * c4) * 4;
                cpa16(kb + off, Kp + (size_t)(nk0 + row) * E_ + 4 * c4);
                cpa16(vb + off, Vp + (size_t)(nk0 + row) * E_ + 4 * c4);
            }
        }
        CPA_COMMIT();
        CPA_WAIT1();           // tile kt's group complete
        __syncthreads();       // all threads' cp.async data visible

        uint32_t* Ks = KV + (uint32_t)s * 2 * ST_U32;
        uint32_t* Vs = Ks + ST_U32;

        // cooperative in-place tf32 conversion (once per CTA, not per warp)
        convert_tile_tf32(Ks, tid);
        convert_tile_tf32(Vs, tid);
        __syncthreads();

        if (q0 + 16 * w + 15 >= kt0) {
            float sacc[8][4];
#pragma unroll
            for (int ni = 0; ni < 8; ni++)
#pragma unroll
                for (int c = 0; c < 4; c++) sacc[ni][c] = 0.f;

#pragma unroll
            for (int ks = 0; ks < 16; ks++) {
#pragma unroll
                for (int ni = 0; ni < 8; ni++) {
                    const uint32_t* kb = Ks + (8 * ni + g) * AK_STR + 8 * ks;
                    uint32_t b[2] = { kb[tg], kb[tg + 4] };
                    mma_tf32(sacc[ni], qf[ks], b);
                }
            }
            // causal + external mask (mask==0 -> -1e9 overrides causal -inf)
#pragma unroll
            for (int ni = 0; ni < 8; ni++) {
                int k1 = kt0 + 8 * ni + 2 * tg;
                int2 ma = *(const int2*)&mask[(size_t)gq1 * T_ + k1];
                int2 mb = *(const int2*)&mask[(size_t)gq2 * T_ + k1];
                if (k1 > gq1)     sacc[ni][0] = -INFINITY;
                if (k1 + 1 > gq1) sacc[ni][1] = -INFINITY;
                if (k1 > gq2)     sacc[ni][2] = -INFINITY;
                if (k1 + 1 > gq2) sacc[ni][3] = -INFINITY;
                if (ma.x == 0) sacc[ni][0] = -1e9f;
                if (ma.y == 0) sacc[ni][1] = -1e9f;
                if (mb.x == 0) sacc[ni][2] = -1e9f;
                if (mb.y == 0) sacc[ni][3] = -1e9f;
            }
            attn_softmax_pv(sacc, m1, m2, l1, l2, o, Ps, Vs, r1, g, tg);
        } else {
            // fully-future tile for this warp: matters only for dead rows
            unsigned anyd = __any_sync(0xffffffffu, (m1 < -1e8f) || (m2 < -1e8f));
            if (anyd) {
                float sacc[8][4];
#pragma unroll
                for (int ni = 0; ni < 8; ni++) {
                    int k1 = kt0 + 8 * ni + 2 * tg;
                    int2 ma = *(const int2*)&mask[(size_t)gq1 * T_ + k1];
                    int2 mb = *(const int2*)&mask[(size_t)gq2 * T_ + k1];
                    sacc[ni][0] = ma.x ? -INFINITY : -1e9f;
                    sacc[ni][1] = ma.y ? -INFINITY : -1e9f;
                    sacc[ni][2] = mb.x ? -INFINITY : -1e9f;
                    sacc[ni][3] = mb.y ? -INFINITY : -1e9f;
                }
                attn_softmax_pv(sacc, m1, m2, l1, l2, o, Ps, Vs, r1, g, tg);
            }
        }
        __syncthreads();   // everyone done reading stage s before reuse
    }

    // Phase B: fully-masked rows attend to future mask==0 positions
    __syncthreads();
    if (tid == 0) *needb = 0;
    __syncthreads();
    if ((m1 < -1e8f) || (m2 < -1e8f)) *needb = 1;
    __syncthreads();
    if (*needb) {
        for (int kt = ntA; kt < T_ / 64; kt++) {
            const int kt0 = kt * 64;
            __syncthreads();
            {
                uint32_t vb = kv_base + ST_U32 * 4;   // V stage 0
#pragma unroll
                for (int i = 0; i < 8; i++) {
                    int f = tid + i * 256;
                    int row = f >> 5, c4 = f & 31;
                    uint32_t off = (uint32_t)(row * AV_STR + 4 * c4) * 4;
                    cpa16(vb + off, Vp + (size_t)(kt0 + row) * E_ + 4 * c4);
                }
                CPA_COMMIT();
                CPA_WAIT0();
            }
            __syncthreads();
            uint32_t* Vs = KV + ST_U32;
            convert_tile_tf32(Vs, tid);
            __syncthreads();
            unsigned anyd = __any_sync(0xffffffffu, (m1 < -1e8f) || (m2 < -1e8f));
            if (anyd) {
                float sacc[8][4];
#pragma unroll
                for (int ni = 0; ni < 8; ni++) {
                    int k1 = kt0 + 8 * ni + 2 * tg;
                    int2 ma = *(const int2*)&mask[(size_t)gq1 * T_ + k1];
                    int2 mb = *(const int2*)&mask[(size_t)gq2 * T_ + k1];
                    sacc[ni][0] = ma.x ? -INFINITY : -1e9f;
                    sacc[ni][1] = ma.y ? -INFINITY : -1e9f;
                    sacc[ni][2] = mb.x ? -INFINITY : -1e9f;
                    sacc[ni][3] = mb.y ? -INFINITY : -1e9f;
                }
                attn_softmax_pv(sacc, m1, m2, l1, l2, o, Ps, Vs, r1, g, tg);
            }
        }
    }

    // epilogue: normalize and write Og[b*t][h*e]
    float inv1 = 1.f / l1, inv2 = 1.f / l2;
    const int b = bh >> 3, h = bh & 7;
    size_t base1 = ((size_t)(b * T_ + gq1)) * EH_ + h * E_;
    size_t base2 = base1 + (size_t)8 * EH_;
#pragma unroll
    for (int ni = 0; ni < 16; ni++) {
        int col = 8 * ni + 2 * tg;
        *(float2*)&Og[base1 + col] = make_float2(o[ni][0] * inv1, o[ni][1] * inv1);
        *(float2*)&Og[base2 + col] = make_float2(o[ni][2] * inv2, o[ni][3] * inv2);
    }
}

// ---------------------------------------------------------------------------
extern "C" void kernel_launch(void* const* d_in, const int* in_sizes, int n_in,
                              void* d_out, int out_size)
{
    const float* x   = (const float*)d_in[0];
    const int*  mask = (const int*)  d_in[1];
    const float* Wq  = (const float*)d_in[2];
    const float* Wk  = (const float*)d_in[3];
    const float* Wv  = (const float*)d_in[4];
    const float* Wu  = (const float*)d_in[5];
    const float* bu  = (const float*)d_in[6];
    float* out = (float*)d_out;

    cudaFuncSetAttribute(attn_kernel,
                         cudaFuncAttributeMaxDynamicSharedMemorySize, SMEM_ATTN);
    cudaFuncSetAttribute(qkv_mma_kernel,
                         cudaFuncAttributeMaxDynamicSharedMemorySize, SMEM_GEMM);
    cudaFuncSetAttribute(out_mma_kernel,
                         cudaFuncAttributeMaxDynamicSharedMemorySize, SMEM_OUT);

    qkv_mma_kernel<<<dim3(M_ / 128, H_, 3), 256, SMEM_GEMM>>>(x, Wq, Wk, Wv);
    attn_kernel<<<dim3(T_ / 128, BH_), 256, SMEM_ATTN>>>(mask);
    out_mma_kernel<<<dim3(M_ / 64, 1, 1), 256, SMEM_OUT>>>(Wu, bu, out);
}

// round 11
// speedup vs baseline: 1.0194x; 1.0194x over previous
#include <cuda_runtime.h>
#include <math.h>
#include <stdint.h>

#define B_  4
#define T_  2048
#define E_  128
#define H_  8
#define BH_ 32
#define M_  8192      // B*T
#define EH_ 1024      // E*H

// total softmax scale: e^-0.5 (folded into Q)
#define S2_ 0.08838834764831845f

// Projection GEMM smem (floats)
#define GA_STR 36
#define GB_STR 136
#define G_AS_FLOATS (128 * GA_STR)
#define G_BS_FLOATS (32 * GB_STR)
#define SMEM_GEMM ((G_AS_FLOATS + G_BS_FLOATS) * 4)     // qkv kernel

#define G_AS2_FLOATS (64 * GA_STR)
#define SMEM_OUT ((G_AS2_FLOATS + G_BS_FLOATS) * 4)     // out kernel (M-tile 64)

// Attention smem (BM=64): K + V (raw fp32 bits) + P (tf32 bits) + flag
#define AK_STR 132
#define AV_STR 132
#define AP_STR 68
#define ST_U32 (64 * AK_STR)                 // one K or V tile
#define SMEM_ATTN ((2 * ST_U32 + 64 * AP_STR + 4) * 4)   // ~85KB -> 2 CTAs/SM

// Scratch (device globals: allowed; runtime alloc is not)
__device__ float Qg[(size_t)BH_ * T_ * E_];   // [bh][t][e]
__device__ float Kg[(size_t)BH_ * T_ * E_];   // [bh][t][e]
__device__ float Vg[(size_t)BH_ * T_ * E_];   // [bh][t][e]
__device__ float Og[(size_t)M_ * EH_];        // [b*t][h*e]

// ---------------------------------------------------------------------------
// helpers (sm_80+ only; toolchain compiles at compute_100 non-a)
// ---------------------------------------------------------------------------
__device__ __forceinline__ uint32_t f2tf32(float f) {
    uint32_t r;
    asm("cvt.rna.tf32.f32 %0, %1;" : "=r"(r) : "f"(f));
    return r;
}
__device__ __forceinline__ void mma_tf32(float* d, const uint32_t* a, const uint32_t* b) {
    asm volatile(
        "mma.sync.aligned.m16n8k8.row.col.f32.tf32.tf32.f32 "
        "{%0,%1,%2,%3}, {%4,%5,%6,%7}, {%8,%9}, {%0,%1,%2,%3};"
        : "+f"(d[0]), "+f"(d[1]), "+f"(d[2]), "+f"(d[3])
        : "r"(a[0]), "r"(a[1]), "r"(a[2]), "r"(a[3]), "r"(b[0]), "r"(b[1]));
}
__device__ __forceinline__ uint32_t smem_u32addr(const void* p) {
    uint32_t a;
    asm("{ .reg .u64 t; cvta.to.shared.u64 t, %1; cvt.u32.u64 %0, t; }"
        : "=r"(a) : "l"(p));
    return a;
}
__device__ __forceinline__ void cpa16(uint32_t s, const void* g) {
    asm volatile("cp.async.cg.shared.global [%0], [%1], 16;" :: "r"(s), "l"(g));
}
#define CPA_COMMIT() asm volatile("cp.async.commit_group;" ::: "memory")
#define CPA_WAIT0()  asm volatile("cp.async.wait_group 0;" ::: "memory")

// ---------------------------------------------------------------------------
// Kernel 1: QKV projection via tf32 mma.sync (unchanged, measured good).
// ---------------------------------------------------------------------------
__global__ __launch_bounds__(256) void qkv_mma_kernel(
    const float* __restrict__ x,
    const float* __restrict__ Wq,
    const float* __restrict__ Wk,
    const float* __restrict__ Wv)
{
    extern __shared__ float sm[];
    uint32_t* AsU = (uint32_t*)sm;
    uint32_t* BsU = (uint32_t*)(sm + G_AS_FLOATS);

    const int z  = blockIdx.z;
    const float* __restrict__ Wp = (z == 0) ? Wq : (z == 1) ? Wk : Wv;
    float* __restrict__ outp     = (z == 0) ? Qg : (z == 1) ? Kg : Vg;
    const int m0 = blockIdx.x * 128;
    const int h  = blockIdx.y;
    const int n0 = h * 128;

    const int tid  = threadIdx.x;
    const int warp = tid >> 5, lane = tid & 31;
    const int g = lane >> 2, tg = lane & 3;
    const int wm0 = (warp & 1) * 64;
    const int wn0 = (warp >> 1) * 32;

    float acc[4][4][4];
#pragma unroll
    for (int mi = 0; mi < 4; mi++)
#pragma unroll
        for (int ni = 0; ni < 4; ni++)
#pragma unroll
            for (int c = 0; c < 4; c++) acc[mi][ni][c] = 0.f;

    for (int kc = 0; kc < 4; kc++) {
        const int k0 = kc * 32;
#pragma unroll
        for (int i = 0; i < 4; i++) {
            int f = tid + i * 256;
            int row = f >> 3, s4 = f & 7;
            float4 v = *(const float4*)&x[(size_t)(m0 + row) * E_ + k0 + 4 * s4];
            AsU[row * GA_STR + 4 * s4 + 0] = f2tf32(v.x);
            AsU[row * GA_STR + 4 * s4 + 1] = f2tf32(v.y);
            AsU[row * GA_STR + 4 * s4 + 2] = f2tf32(v.z);
            AsU[row * GA_STR + 4 * s4 + 3] = f2tf32(v.w);
        }
#pragma unroll
        for (int i = 0; i < 4; i++) {
            int f = tid + i * 256;
            int kk = f >> 5, n4 = f & 31;
            float4 v = *(const float4*)&Wp[(size_t)(k0 + kk) * EH_ + n0 + 4 * n4];
            BsU[kk * GB_STR + 4 * n4 + 0] = f2tf32(v.x);
            BsU[kk * GB_STR + 4 * n4 + 1] = f2tf32(v.y);
            BsU[kk * GB_STR + 4 * n4 + 2] = f2tf32(v.z);
            BsU[kk * GB_STR + 4 * n4 + 3] = f2tf32(v.w);
        }
        __syncthreads();

#pragma unroll
        for (int ks = 0; ks < 4; ks++) {
            const int kb = 8 * ks;
            uint32_t a[4][4], b[4][2];
#pragma unroll
            for (int mi = 0; mi < 4; mi++) {
                int r = wm0 + 16 * mi + g;
                a[mi][0] = AsU[r * GA_STR + kb + tg];
                a[mi][1] = AsU[(r + 8) * GA_STR + kb + tg];
                a[mi][2] = AsU[r * GA_STR + kb + tg + 4];
                a[mi][3] = AsU[(r + 8) * GA_STR + kb + tg + 4];
            }
#pragma unroll
            for (int ni = 0; ni < 4; ni++) {
                int col = wn0 + 8 * ni + g;
                b[ni][0] = BsU[(kb + tg) * GB_STR + col];
                b[ni][1] = BsU[(kb + tg + 4) * GB_STR + col];
            }
#pragma unroll
            for (int mi = 0; mi < 4; mi++)
#pragma unroll
                for (int ni = 0; ni < 4; ni++)
                    mma_tf32(acc[mi][ni], a[mi], b[ni]);
        }
        __syncthreads();
    }

    const int b_ = m0 >> 11;
    const int t0 = m0 & 2047;
#pragma unroll
    for (int mi = 0; mi < 4; mi++) {
        int rl = wm0 + 16 * mi + g;
        size_t rbase = ((size_t)(b_ * H_ + h) * T_ + t0 + rl) * E_;
#pragma unroll
        for (int ni = 0; ni < 4; ni++) {
            int n = wn0 + 8 * ni + 2 * tg;
            *(float2*)&outp[rbase + n] =
                make_float2(acc[mi][ni][0], acc[mi][ni][1]);
            *(float2*)&outp[rbase + 8 * E_ + n] =
                make_float2(acc[mi][ni][2], acc[mi][ni][3]);
        }
    }
}

// ---------------------------------------------------------------------------
// Kernel 3: output projection, M-tile 64 (unchanged, measured good).
// ---------------------------------------------------------------------------
__global__ __launch_bounds__(256) void out_mma_kernel(
    const float* __restrict__ Wu,
    const float* __restrict__ bu,
    float* __restrict__ out)
{
    extern __shared__ float sm[];
    uint32_t* AsU = (uint32_t*)sm;                   // [64][36]
    uint32_t* BsU = (uint32_t*)(sm + G_AS2_FLOATS);  // [32][136]

    const int m0 = blockIdx.x * 64;
    const int tid  = threadIdx.x;
    const int warp = tid >> 5, lane = tid & 31;
    const int g = lane >> 2, tg = lane & 3;
    const int wm0 = (warp & 1) * 32;
    const int wn0 = (warp >> 1) * 32;

    float acc[2][4][4];
#pragma unroll
    for (int mi = 0; mi < 2; mi++)
#pragma unroll
        for (int ni = 0; ni < 4; ni++)
#pragma unroll
            for (int c = 0; c < 4; c++) acc[mi][ni][c] = 0.f;

    for (int kc = 0; kc < 32; kc++) {
        const int k0 = kc * 32;
#pragma unroll
        for (int i = 0; i < 2; i++) {
            int f = tid + i * 256;
            int row = f >> 3, s4 = f & 7;
            float4 v = *(const float4*)&Og[(size_t)(m0 + row) * EH_ + k0 + 4 * s4];
            AsU[row * GA_STR + 4 * s4 + 0] = f2tf32(v.x);
            AsU[row * GA_STR + 4 * s4 + 1] = f2tf32(v.y);
            AsU[row * GA_STR + 4 * s4 + 2] = f2tf32(v.z);
            AsU[row * GA_STR + 4 * s4 + 3] = f2tf32(v.w);
        }
#pragma unroll
        for (int i = 0; i < 4; i++) {
            int f = tid + i * 256;
            int kk = f >> 5, n4 = f & 31;
            float4 v = *(const float4*)&Wu[(size_t)(k0 + kk) * E_ + 4 * n4];
            BsU[kk * GB_STR + 4 * n4 + 0] = f2tf32(v.x);
            BsU[kk * GB_STR + 4 * n4 + 1] = f2tf32(v.y);
            BsU[kk * GB_STR + 4 * n4 + 2] = f2tf32(v.z);
            BsU[kk * GB_STR + 4 * n4 + 3] = f2tf32(v.w);
        }
        __syncthreads();

#pragma unroll
        for (int ks = 0; ks < 4; ks++) {
            const int kb = 8 * ks;
            uint32_t a[2][4], b[4][2];
#pragma unroll
            for (int mi = 0; mi < 2; mi++) {
                int r = wm0 + 16 * mi + g;
                a[mi][0] = AsU[r * GA_STR + kb + tg];
                a[mi][1] = AsU[(r + 8) * GA_STR + kb + tg];
                a[mi][2] = AsU[r * GA_STR + kb + tg + 4];
                a[mi][3] = AsU[(r + 8) * GA_STR + kb + tg + 4];
            }
#pragma unroll
            for (int ni = 0; ni < 4; ni++) {
                int col = wn0 + 8 * ni + g;
                b[ni][0] = BsU[(kb + tg) * GB_STR + col];
                b[ni][1] = BsU[(kb + tg + 4) * GB_STR + col];
            }
#pragma unroll
            for (int mi = 0; mi < 2; mi++)
#pragma unroll
                for (int ni = 0; ni < 4; ni++)
                    mma_tf32(acc[mi][ni], a[mi], b[ni]);
        }
        __syncthreads();
    }

#pragma unroll
    for (int mi = 0; mi < 2; mi++) {
        int m = m0 + wm0 + 16 * mi + g;
#pragma unroll
        for (int ni = 0; ni < 4; ni++) {
            int n = wn0 + 8 * ni + 2 * tg;
            float2 bias = *(const float2*)&bu[n];
            *(float2*)&out[(size_t)m * E_ + n] =
                make_float2(acc[mi][ni][0] + bias.x, acc[mi][ni][1] + bias.y);
            *(float2*)&out[(size_t)(m + 8) * E_ + n] =
                make_float2(acc[mi][ni][2] + bias.x, acc[mi][ni][3] + bias.y);
        }
    }
}

// ---------------------------------------------------------------------------
// Attention softmax + PV (R8 semantics: V raw in smem, cvt at frag load).
// ---------------------------------------------------------------------------
__device__ __forceinline__ void attn_softmax_pv(
    float sacc[8][4], float& m1, float& m2, float& l1, float& l2,
    float o[16][4], uint32_t* Ps, const uint32_t* Vs, int r1, int g, int tg)
{
    float mt1 = -INFINITY, mt2 = -INFINITY;
#pragma unroll
    for (int ni = 0; ni < 8; ni++) {
        mt1 = fmaxf(mt1, fmaxf(sacc[ni][0], sacc[ni][1]));
        mt2 = fmaxf(mt2, fmaxf(sacc[ni][2], sacc[ni][3]));
    }
    mt1 = fmaxf(mt1, __shfl_xor_sync(0xffffffffu, mt1, 1));
    mt1 = fmaxf(mt1, __shfl_xor_sync(0xffffffffu, mt1, 2));
    mt2 = fmaxf(mt2, __shfl_xor_sync(0xffffffffu, mt2, 1));
    mt2 = fmaxf(mt2, __shfl_xor_sync(0xffffffffu, mt2, 2));
    float mn1 = fmaxf(m1, mt1), mn2 = fmaxf(m2, mt2);
    float al1 = (m1 == mn1) ? 1.f : __expf(m1 - mn1);
    float al2 = (m2 == mn2) ? 1.f : __expf(m2 - mn2);
    float me1 = (mn1 == -INFINITY) ? 0.f : mn1;
    float me2 = (mn2 == -INFINITY) ? 0.f : mn2;
    float ls1 = 0.f, ls2 = 0.f;
#pragma unroll
    for (int ni = 0; ni < 8; ni++) {
        float p0 = __expf(sacc[ni][0] - me1);
        float p1 = __expf(sacc[ni][1] - me1);
        float p2 = __expf(sacc[ni][2] - me2);
        float p3 = __expf(sacc[ni][3] - me2);
        ls1 += p0 + p1; ls2 += p2 + p3;
        uint32_t* pb = Ps + r1 * AP_STR + 8 * ni + 2 * tg;
        pb[0] = f2tf32(p0); pb[1] = f2tf32(p1);
        pb[8 * AP_STR] = f2tf32(p2); pb[8 * AP_STR + 1] = f2tf32(p3);
    }
    ls1 += __shfl_xor_sync(0xffffffffu, ls1, 1);
    ls1 += __shfl_xor_sync(0xffffffffu, ls1, 2);
    ls2 += __shfl_xor_sync(0xffffffffu, ls2, 1);
    ls2 += __shfl_xor_sync(0xffffffffu, ls2, 2);
    l1 = l1 * al1 + ls1; m1 = mn1;
    l2 = l2 * al2 + ls2; m2 = mn2;
#pragma unroll
    for (int ni = 0; ni < 16; ni++) {
        o[ni][0] *= al1; o[ni][1] *= al1;
        o[ni][2] *= al2; o[ni][3] *= al2;
    }
    __syncwarp();
#pragma unroll
    for (int kp = 0; kp < 8; kp++) {
        uint32_t a[4];
        const uint32_t* pb = Ps + r1 * AP_STR + 8 * kp;
        a[0] = pb[tg]; a[1] = pb[8 * AP_STR + tg];
        a[2] = pb[tg + 4]; a[3] = pb[8 * AP_STR + tg + 4];
#pragma unroll
        for (int ni = 0; ni < 16; ni++) {
            const uint32_t* vb = Vs + (8 * kp + tg) * AV_STR + 8 * ni + g;
            uint32_t b[2] = { f2tf32(__uint_as_float(vb[0])),
                              f2tf32(__uint_as_float(vb[4 * AV_STR])) };
            mma_tf32(o[ni], a, b);
        }
    }
    __syncwarp();   // all lanes done reading Ps before next tile overwrites
}

// ---------------------------------------------------------------------------
// Kernel 2: flash attention. BM=64, BN=64, 128 threads (4 warps), 2 CTAs/SM.
// Single-buffered cp.async K/V — the co-resident CTA hides load latency.
// Q in registers. Numerics identical to R8.
// ---------------------------------------------------------------------------
__global__ __launch_bounds__(128, 2) void attn_kernel(const int* __restrict__ mask)
{
    extern __shared__ uint32_t smu[];
    uint32_t* Ks = smu;                       // [64][132] raw fp32 bits
    uint32_t* Vs = smu + ST_U32;              // [64][132]
    uint32_t* Ps = smu + 2 * ST_U32;          // [64][68] tf32 bits
    int* needb = (int*)(Ps + 64 * AP_STR);

    const int bh = blockIdx.y;
    const int qt = (gridDim.x - 1) - blockIdx.x;   // heavy blocks first
    const int q0 = qt * 64;
    const int tid = threadIdx.x;
    const int w = tid >> 5, lane = tid & 31;
    const int g = lane >> 2, tg = lane & 3;
    const int r1 = 16 * w + g;                     // local rows r1, r1+8 (0..63)
    const int gq1 = q0 + r1, gq2 = gq1 + 8;

    const float* __restrict__ Qp = Qg + (size_t)bh * T_ * E_;
    const float* __restrict__ Kp = Kg + (size_t)bh * T_ * E_;
    const float* __restrict__ Vp = Vg + (size_t)bh * T_ * E_;

    const uint32_t k_base = smem_u32addr(Ks);
    const uint32_t v_base = smem_u32addr(Vs);

    // --- stage Q (64x128) through Ks area, convert + scale, pull frags
#pragma unroll
    for (int i = 0; i < 16; i++) {
        int f = tid + i * 128;                // 0..2047 float4 slots
        int row = f >> 5, c4 = f & 31;
        float4 v = *(const float4*)&Qp[(size_t)(q0 + row) * E_ + 4 * c4];
        uint32_t* d = Ks + row * AK_STR + 4 * c4;
        d[0] = f2tf32(v.x * S2_); d[1] = f2tf32(v.y * S2_);
        d[2] = f2tf32(v.z * S2_); d[3] = f2tf32(v.w * S2_);
    }
    __syncthreads();
    uint32_t qf[16][4];
#pragma unroll
    for (int ks = 0; ks < 16; ks++) {
        const uint32_t* qb = Ks + r1 * AK_STR + 8 * ks;
        qf[ks][0] = qb[tg];
        qf[ks][1] = qb[8 * AK_STR + tg];
        qf[ks][2] = qb[tg + 4];
        qf[ks][3] = qb[8 * AK_STR + tg + 4];
    }
    __syncthreads();   // done reading staging area before loads overwrite

    float o[16][4];
#pragma unroll
    for (int ni = 0; ni < 16; ni++)
#pragma unroll
        for (int c = 0; c < 4; c++) o[ni][c] = 0.f;

    float m1 = -INFINITY, m2 = -INFINITY, l1 = 0.f, l2 = 0.f;
    const int ntA = qt + 1;

    for (int kt = 0; kt < ntA; kt++) {
        const int kt0 = kt * 64;

        // load K,V tile kt (single buffer; other CTA hides the wait)
#pragma unroll
        for (int i = 0; i < 16; i++) {
            int f = tid + i * 128;
            int row = f >> 5, c4 = f & 31;
            uint32_t off = (uint32_t)(row * AK_STR + 4 * c4) * 4;
            cpa16(k_base + off, Kp + (size_t)(kt0 + row) * E_ + 4 * c4);
            cpa16(v_base + off, Vp + (size_t)(kt0 + row) * E_ + 4 * c4);
        }
        CPA_COMMIT();
        CPA_WAIT0();
        __syncthreads();

        if (q0 + 16 * w + 15 >= kt0) {
            float sacc[8][4];
#pragma unroll
            for (int ni = 0; ni < 8; ni++)
#pragma unroll
                for (int c = 0; c < 4; c++) sacc[ni][c] = 0.f;

#pragma unroll
            for (int ks = 0; ks < 16; ks++) {
#pragma unroll
                for (int ni = 0; ni < 8; ni++) {
                    const uint32_t* kb = Ks + (8 * ni + g) * AK_STR + 8 * ks;
                    uint32_t b[2] = { f2tf32(__uint_as_float(kb[tg])),
                                      f2tf32(__uint_as_float(kb[tg + 4])) };
                    mma_tf32(sacc[ni], qf[ks], b);
                }
            }
            // causal + external mask (mask==0 -> -1e9 overrides causal -inf)
#pragma unroll
            for (int ni = 0; ni < 8; ni++) {
                int k1 = kt0 + 8 * ni + 2 * tg;
                int2 ma = *(const int2*)&mask[(size_t)gq1 * T_ + k1];
                int2 mb = *(const int2*)&mask[(size_t)gq2 * T_ + k1];
                if (k1 > gq1)     sacc[ni][0] = -INFINITY;
                if (k1 + 1 > gq1) sacc[ni][1] = -INFINITY;
                if (k1 > gq2)     sacc[ni][2] = -INFINITY;
                if (k1 + 1 > gq2) sacc[ni][3] = -INFINITY;
                if (ma.x == 0) sacc[ni][0] = -1e9f;
                if (ma.y == 0) sacc[ni][1] = -1e9f;
                if (mb.x == 0) sacc[ni][2] = -1e9f;
                if (mb.y == 0) sacc[ni][3] = -1e9f;
            }
            attn_softmax_pv(sacc, m1, m2, l1, l2, o, Ps, Vs, r1, g, tg);
        } else {
            // fully-future tile for this warp: matters only for dead rows
            unsigned anyd = __any_sync(0xffffffffu, (m1 < -1e8f) || (m2 < -1e8f));
            if (anyd) {
                float sacc[8][4];
#pragma unroll
                for (int ni = 0; ni < 8; ni++) {
                    int k1 = kt0 + 8 * ni + 2 * tg;
                    int2 ma = *(const int2*)&mask[(size_t)gq1 * T_ + k1];
                    int2 mb = *(const int2*)&mask[(size_t)gq2 * T_ + k1];
                    sacc[ni][0] = ma.x ? -INFINITY : -1e9f;
                    sacc[ni][1] = ma.y ? -INFINITY : -1e9f;
                    sacc[ni][2] = mb.x ? -INFINITY : -1e9f;
                    sacc[ni][3] = mb.y ? -INFINITY : -1e9f;
                }
                attn_softmax_pv(sacc, m1, m2, l1, l2, o, Ps, Vs, r1, g, tg);
            }
        }
        __syncthreads();   // everyone done reading K/V before next load
    }

    // Phase B: fully-masked rows attend to future mask==0 positions
    if (tid == 0) *needb = 0;
    __syncthreads();
    if ((m1 < -1e8f) || (m2 < -1e8f)) *needb = 1;
    __syncthreads();
    if (*needb) {
        for (int kt = ntA; kt < T_ / 64; kt++) {
            const int kt0 = kt * 64;
#pragma unroll
            for (int i = 0; i < 16; i++) {
                int f = tid + i * 128;
                int row = f >> 5, c4 = f & 31;
                uint32_t off = (uint32_t)(row * AV_STR + 4 * c4) * 4;
                cpa16(v_base + off, Vp + (size_t)(kt0 + row) * E_ + 4 * c4);
            }
            CPA_COMMIT();
            CPA_WAIT0();
            __syncthreads();
            unsigned anyd = __any_sync(0xffffffffu, (m1 < -1e8f) || (m2 < -1e8f));
            if (anyd) {
                float sacc[8][4];
#pragma unroll
                for (int ni = 0; ni < 8; ni++) {
                    int k1 = kt0 + 8 * ni + 2 * tg;
                    int2 ma = *(const int2*)&mask[(size_t)gq1 * T_ + k1];
                    int2 mb = *(const int2*)&mask[(size_t)gq2 * T_ + k1];
                    sacc[ni][0] = ma.x ? -INFINITY : -1e9f;
                    sacc[ni][1] = ma.y ? -INFINITY : -1e9f;
                    sacc[ni][2] = mb.x ? -INFINITY : -1e9f;
                    sacc[ni][3] = mb.y ? -INFINITY : -1e9f;
                }
                attn_softmax_pv(sacc, m1, m2, l1, l2, o, Ps, Vs, r1, g, tg);
            }
            __syncthreads();
        }
    }

    // epilogue: normalize and write Og[b*t][h*e]
    float inv1 = 1.f / l1, inv2 = 1.f / l2;
    const int b = bh >> 3, h = bh & 7;
    size_t base1 = ((size_t)(b * T_ + gq1)) * EH_ + h * E_;
    size_t base2 = base1 + (size_t)8 * EH_;
#pragma unroll
    for (int ni = 0; ni < 16; ni++) {
        int col = 8 * ni + 2 * tg;
        *(float2*)&Og[base1 + col] = make_float2(o[ni][0] * inv1, o[ni][1] * inv1);
        *(float2*)&Og[base2 + col] = make_float2(o[ni][2] * inv2, o[ni][3] * inv2);
    }
}

// ---------------------------------------------------------------------------
extern "C" void kernel_launch(void* const* d_in, const int* in_sizes, int n_in,
                              void* d_out, int out_size)
{
    const float* x   = (const float*)d_in[0];
    const int*  mask = (const int*)  d_in[1];
    const float* Wq  = (const float*)d_in[2];
    const float* Wk  = (const float*)d_in[3];
    const float* Wv  = (const float*)d_in[4];
    const float* Wu  = (const float*)d_in[5];
    const float* bu  = (const float*)d_in[6];
    float* out = (float*)d_out;

    cudaFuncSetAttribute(attn_kernel,
                         cudaFuncAttributeMaxDynamicSharedMemorySize, SMEM_ATTN);
    cudaFuncSetAttribute(qkv_mma_kernel,
                         cudaFuncAttributeMaxDynamicSharedMemorySize, SMEM_GEMM);
    cudaFuncSetAttribute(out_mma_kernel,
                         cudaFuncAttributeMaxDynamicSharedMemorySize, SMEM_OUT);

    qkv_mma_kernel<<<dim3(M_ / 128, H_, 3), 256, SMEM_GEMM>>>(x, Wq, Wk, Wv);
    attn_kernel<<<dim3(T_ / 64, BH_), 128, SMEM_ATTN>>>(mask);
    out_mma_kernel<<<dim3(M_ / 64, 1, 1), 256, SMEM_OUT>>>(Wu, bu, out);
}

// round 12
// speedup vs baseline: 1.0610x; 1.0408x over previous
#include <cuda_runtime.h>
#include <math.h>
#include <stdint.h>

#define B_  4
#define T_  2048
#define E_  128
#define H_  8
#define BH_ 32
#define M_  8192      // B*T
#define EH_ 1024      // E*H

// total softmax scale: e^-0.5 (folded into Q)
#define S2_ 0.08838834764831845f

// Projection GEMM smem (floats)
#define GA_STR 36
#define GB_STR 136
#define G_AS_FLOATS (128 * GA_STR)
#define G_BS_FLOATS (32 * GB_STR)
#define SMEM_GEMM ((G_AS_FLOATS + G_BS_FLOATS) * 4)     // qkv kernel

#define G_AS2_FLOATS (64 * GA_STR)
#define SMEM_OUT ((G_AS2_FLOATS + G_BS_FLOATS) * 4)     // out kernel (M-tile 64)

// Attention smem (BM=64): K + V (raw fp32 bits) + P (tf32 bits) + flag
#define AK_STR 132
#define AV_STR 132
#define AP_STR 68
#define ST_U32 (64 * AK_STR)                 // one K or V tile
#define SMEM_ATTN ((2 * ST_U32 + 64 * AP_STR + 4) * 4)   // ~85KB -> 2 CTAs/SM

// Scratch (device globals: allowed; runtime alloc is not)
__device__ float Qg[(size_t)BH_ * T_ * E_];   // [bh][t][e]
__device__ float Kg[(size_t)BH_ * T_ * E_];   // [bh][t][e]
__device__ float Vg[(size_t)BH_ * T_ * E_];   // [bh][t][e]
__device__ float Og[(size_t)M_ * EH_];        // [b*t][h*e]

// ---------------------------------------------------------------------------
// helpers (sm_80+ only; toolchain compiles at compute_100 non-a)
// ---------------------------------------------------------------------------
__device__ __forceinline__ uint32_t f2tf32(float f) {
    uint32_t r;
    asm("cvt.rna.tf32.f32 %0, %1;" : "=r"(r) : "f"(f));
    return r;
}
__device__ __forceinline__ void mma_tf32(float* d, const uint32_t* a, const uint32_t* b) {
    asm volatile(
        "mma.sync.aligned.m16n8k8.row.col.f32.tf32.tf32.f32 "
        "{%0,%1,%2,%3}, {%4,%5,%6,%7}, {%8,%9}, {%0,%1,%2,%3};"
        : "+f"(d[0]), "+f"(d[1]), "+f"(d[2]), "+f"(d[3])
        : "r"(a[0]), "r"(a[1]), "r"(a[2]), "r"(a[3]), "r"(b[0]), "r"(b[1]));
}
__device__ __forceinline__ uint32_t smem_u32addr(const void* p) {
    uint32_t a;
    asm("{ .reg .u64 t; cvta.to.shared.u64 t, %1; cvt.u32.u64 %0, t; }"
        : "=r"(a) : "l"(p));
    return a;
}
__device__ __forceinline__ void cpa16(uint32_t s, const void* g) {
    asm volatile("cp.async.cg.shared.global [%0], [%1], 16;" :: "r"(s), "l"(g));
}
#define CPA_COMMIT() asm volatile("cp.async.commit_group;" ::: "memory")
#define CPA_WAIT1()  asm volatile("cp.async.wait_group 1;" ::: "memory")
#define CPA_WAIT0()  asm volatile("cp.async.wait_group 0;" ::: "memory")

// ---------------------------------------------------------------------------
// Kernel 1: QKV projection via tf32 mma.sync (unchanged, measured good).
// ---------------------------------------------------------------------------
__global__ __launch_bounds__(256) void qkv_mma_kernel(
    const float* __restrict__ x,
    const float* __restrict__ Wq,
    const float* __restrict__ Wk,
    const float* __restrict__ Wv)
{
    extern __shared__ float sm[];
    uint32_t* AsU = (uint32_t*)sm;
    uint32_t* BsU = (uint32_t*)(sm + G_AS_FLOATS);

    const int z  = blockIdx.z;
    const float* __restrict__ Wp = (z == 0) ? Wq : (z == 1) ? Wk : Wv;
    float* __restrict__ outp     = (z == 0) ? Qg : (z == 1) ? Kg : Vg;
    const int m0 = blockIdx.x * 128;
    const int h  = blockIdx.y;
    const int n0 = h * 128;

    const int tid  = threadIdx.x;
    const int warp = tid >> 5, lane = tid & 31;
    const int g = lane >> 2, tg = lane & 3;
    const int wm0 = (warp & 1) * 64;
    const int wn0 = (warp >> 1) * 32;

    float acc[4][4][4];
#pragma unroll
    for (int mi = 0; mi < 4; mi++)
#pragma unroll
        for (int ni = 0; ni < 4; ni++)
#pragma unroll
            for (int c = 0; c < 4; c++) acc[mi][ni][c] = 0.f;

    for (int kc = 0; kc < 4; kc++) {
        const int k0 = kc * 32;
#pragma unroll
        for (int i = 0; i < 4; i++) {
            int f = tid + i * 256;
            int row = f >> 3, s4 = f & 7;
            float4 v = *(const float4*)&x[(size_t)(m0 + row) * E_ + k0 + 4 * s4];
            AsU[row * GA_STR + 4 * s4 + 0] = f2tf32(v.x);
            AsU[row * GA_STR + 4 * s4 + 1] = f2tf32(v.y);
            AsU[row * GA_STR + 4 * s4 + 2] = f2tf32(v.z);
            AsU[row * GA_STR + 4 * s4 + 3] = f2tf32(v.w);
        }
#pragma unroll
        for (int i = 0; i < 4; i++) {
            int f = tid + i * 256;
            int kk = f >> 5, n4 = f & 31;
            float4 v = *(const float4*)&Wp[(size_t)(k0 + kk) * EH_ + n0 + 4 * n4];
            BsU[kk * GB_STR + 4 * n4 + 0] = f2tf32(v.x);
            BsU[kk * GB_STR + 4 * n4 + 1] = f2tf32(v.y);
            BsU[kk * GB_STR + 4 * n4 + 2] = f2tf32(v.z);
            BsU[kk * GB_STR + 4 * n4 + 3] = f2tf32(v.w);
        }
        __syncthreads();

#pragma unroll
        for (int ks = 0; ks < 4; ks++) {
            const int kb = 8 * ks;
            uint32_t a[4][4], b[4][2];
#pragma unroll
            for (int mi = 0; mi < 4; mi++) {
                int r = wm0 + 16 * mi + g;
                a[mi][0] = AsU[r * GA_STR + kb + tg];
                a[mi][1] = AsU[(r + 8) * GA_STR + kb + tg];
                a[mi][2] = AsU[r * GA_STR + kb + tg + 4];
                a[mi][3] = AsU[(r + 8) * GA_STR + kb + tg + 4];
            }
#pragma unroll
            for (int ni = 0; ni < 4; ni++) {
                int col = wn0 + 8 * ni + g;
                b[ni][0] = BsU[(kb + tg) * GB_STR + col];
                b[ni][1] = BsU[(kb + tg + 4) * GB_STR + col];
            }
#pragma unroll
            for (int mi = 0; mi < 4; mi++)
#pragma unroll
                for (int ni = 0; ni < 4; ni++)
                    mma_tf32(acc[mi][ni], a[mi], b[ni]);
        }
        __syncthreads();
    }

    const int b_ = m0 >> 11;
    const int t0 = m0 & 2047;
#pragma unroll
    for (int mi = 0; mi < 4; mi++) {
        int rl = wm0 + 16 * mi + g;
        size_t rbase = ((size_t)(b_ * H_ + h) * T_ + t0 + rl) * E_;
#pragma unroll
        for (int ni = 0; ni < 4; ni++) {
            int n = wn0 + 8 * ni + 2 * tg;
            *(float2*)&outp[rbase + n] =
                make_float2(acc[mi][ni][0], acc[mi][ni][1]);
            *(float2*)&outp[rbase + 8 * E_ + n] =
                make_float2(acc[mi][ni][2], acc[mi][ni][3]);
        }
    }
}

// ---------------------------------------------------------------------------
// Kernel 3: output projection, M-tile 64 (unchanged, measured good).
// ---------------------------------------------------------------------------
__global__ __launch_bounds__(256) void out_mma_kernel(
    const float* __restrict__ Wu,
    const float* __restrict__ bu,
    float* __restrict__ out)
{
    extern __shared__ float sm[];
    uint32_t* AsU = (uint32_t*)sm;                   // [64][36]
    uint32_t* BsU = (uint32_t*)(sm + G_AS2_FLOATS);  // [32][136]

    const int m0 = blockIdx.x * 64;
    const int tid  = threadIdx.x;
    const int warp = tid >> 5, lane = tid & 31;
    const int g = lane >> 2, tg = lane & 3;
    const int wm0 = (warp & 1) * 32;
    const int wn0 = (warp >> 1) * 32;

    float acc[2][4][4];
#pragma unroll
    for (int mi = 0; mi < 2; mi++)
#pragma unroll
        for (int ni = 0; ni < 4; ni++)
#pragma unroll
            for (int c = 0; c < 4; c++) acc[mi][ni][c] = 0.f;

    for (int kc = 0; kc < 32; kc++) {
        const int k0 = kc * 32;
#pragma unroll
        for (int i = 0; i < 2; i++) {
            int f = tid + i * 256;
            int row = f >> 3, s4 = f & 7;
            float4 v = *(const float4*)&Og[(size_t)(m0 + row) * EH_ + k0 + 4 * s4];
            AsU[row * GA_STR + 4 * s4 + 0] = f2tf32(v.x);
            AsU[row * GA_STR + 4 * s4 + 1] = f2tf32(v.y);
            AsU[row * GA_STR + 4 * s4 + 2] = f2tf32(v.z);
            AsU[row * GA_STR + 4 * s4 + 3] = f2tf32(v.w);
        }
#pragma unroll
        for (int i = 0; i < 4; i++) {
            int f = tid + i * 256;
            int kk = f >> 5, n4 = f & 31;
            float4 v = *(const float4*)&Wu[(size_t)(k0 + kk) * E_ + 4 * n4];
            BsU[kk * GB_STR + 4 * n4 + 0] = f2tf32(v.x);
            BsU[kk * GB_STR + 4 * n4 + 1] = f2tf32(v.y);
            BsU[kk * GB_STR + 4 * n4 + 2] = f2tf32(v.z);
            BsU[kk * GB_STR + 4 * n4 + 3] = f2tf32(v.w);
        }
        __syncthreads();

#pragma unroll
        for (int ks = 0; ks < 4; ks++) {
            const int kb = 8 * ks;
            uint32_t a[2][4], b[4][2];
#pragma unroll
            for (int mi = 0; mi < 2; mi++) {
                int r = wm0 + 16 * mi + g;
                a[mi][0] = AsU[r * GA_STR + kb + tg];
                a[mi][1] = AsU[(r + 8) * GA_STR + kb + tg];
                a[mi][2] = AsU[r * GA_STR + kb + tg + 4];
                a[mi][3] = AsU[(r + 8) * GA_STR + kb + tg + 4];
            }
#pragma unroll
            for (int ni = 0; ni < 4; ni++) {
                int col = wn0 + 8 * ni + g;
                b[ni][0] = BsU[(kb + tg) * GB_STR + col];
                b[ni][1] = BsU[(kb + tg + 4) * GB_STR + col];
            }
#pragma unroll
            for (int mi = 0; mi < 2; mi++)
#pragma unroll
                for (int ni = 0; ni < 4; ni++)
                    mma_tf32(acc[mi][ni], a[mi], b[ni]);
        }
        __syncthreads();
    }

#pragma unroll
    for (int mi = 0; mi < 2; mi++) {
        int m = m0 + wm0 + 16 * mi + g;
#pragma unroll
        for (int ni = 0; ni < 4; ni++) {
            int n = wn0 + 8 * ni + 2 * tg;
            float2 bias = *(const float2*)&bu[n];
            *(float2*)&out[(size_t)m * E_ + n] =
                make_float2(acc[mi][ni][0] + bias.x, acc[mi][ni][1] + bias.y);
            *(float2*)&out[(size_t)(m + 8) * E_ + n] =
                make_float2(acc[mi][ni][2] + bias.x, acc[mi][ni][3] + bias.y);
        }
    }
}

// ---------------------------------------------------------------------------
// Attention softmax (updates m/l, scales o, writes P to smem) — V-independent.
// ---------------------------------------------------------------------------
__device__ __forceinline__ void attn_softmax(
    float sacc[8][4], float& m1, float& m2, float& l1, float& l2,
    float o[16][4], uint32_t* Ps, int r1, int tg)
{
    float mt1 = -INFINITY, mt2 = -INFINITY;
#pragma unroll
    for (int ni = 0; ni < 8; ni++) {
        mt1 = fmaxf(mt1, fmaxf(sacc[ni][0], sacc[ni][1]));
        mt2 = fmaxf(mt2, fmaxf(sacc[ni][2], sacc[ni][3]));
    }
    mt1 = fmaxf(mt1, __shfl_xor_sync(0xffffffffu, mt1, 1));
    mt1 = fmaxf(mt1, __shfl_xor_sync(0xffffffffu, mt1, 2));
    mt2 = fmaxf(mt2, __shfl_xor_sync(0xffffffffu, mt2, 1));
    mt2 = fmaxf(mt2, __shfl_xor_sync(0xffffffffu, mt2, 2));
    float mn1 = fmaxf(m1, mt1), mn2 = fmaxf(m2, mt2);
    float al1 = (m1 == mn1) ? 1.f : __expf(m1 - mn1);
    float al2 = (m2 == mn2) ? 1.f : __expf(m2 - mn2);
    float me1 = (mn1 == -INFINITY) ? 0.f : mn1;
    float me2 = (mn2 == -INFINITY) ? 0.f : mn2;
    float ls1 = 0.f, ls2 = 0.f;
#pragma unroll
    for (int ni = 0; ni < 8; ni++) {
        float p0 = __expf(sacc[ni][0] - me1);
        float p1 = __expf(sacc[ni][1] - me1);
        float p2 = __expf(sacc[ni][2] - me2);
        float p3 = __expf(sacc[ni][3] - me2);
        ls1 += p0 + p1; ls2 += p2 + p3;
        uint32_t* pb = Ps + r1 * AP_STR + 8 * ni + 2 * tg;
        pb[0] = f2tf32(p0); pb[1] = f2tf32(p1);
        pb[8 * AP_STR] = f2tf32(p2); pb[8 * AP_STR + 1] = f2tf32(p3);
    }
    ls1 += __shfl_xor_sync(0xffffffffu, ls1, 1);
    ls1 += __shfl_xor_sync(0xffffffffu, ls1, 2);
    ls2 += __shfl_xor_sync(0xffffffffu, ls2, 1);
    ls2 += __shfl_xor_sync(0xffffffffu, ls2, 2);
    l1 = l1 * al1 + ls1; m1 = mn1;
    l2 = l2 * al2 + ls2; m2 = mn2;
#pragma unroll
    for (int ni = 0; ni < 16; ni++) {
        o[ni][0] *= al1; o[ni][1] *= al1;
        o[ni][2] *= al2; o[ni][3] *= al2;
    }
    __syncwarp();   // Ps writes visible warp-wide before PV frag loads
}

// PV: O += P @ V (V raw fp32 in smem, cvt at frag load — R8 semantics).
__device__ __forceinline__ void attn_pv(
    float o[16][4], const uint32_t* Ps, const uint32_t* Vs, int r1, int g, int tg)
{
#pragma unroll
    for (int kp = 0; kp < 8; kp++) {
        uint32_t a[4];
        const uint32_t* pb = Ps + r1 * AP_STR + 8 * kp;
        a[0] = pb[tg]; a[1] = pb[8 * AP_STR + tg];
        a[2] = pb[tg + 4]; a[3] = pb[8 * AP_STR + tg + 4];
#pragma unroll
        for (int ni = 0; ni < 16; ni++) {
            const uint32_t* vb = Vs + (8 * kp + tg) * AV_STR + 8 * ni + g;
            uint32_t b[2] = { f2tf32(__uint_as_float(vb[0])),
                              f2tf32(__uint_as_float(vb[4 * AV_STR])) };
            mma_tf32(o[ni], a, b);
        }
    }
    __syncwarp();   // all lanes done reading Ps before next tile overwrites
}

// ---------------------------------------------------------------------------
// Kernel 2: flash attention. BM=64, 128 threads, 2 CTAs/SM.
// Staggered pipeline: K buffer refilled during softmax, V during next S.
// ---------------------------------------------------------------------------
__global__ __launch_bounds__(128, 2) void attn_kernel(const int* __restrict__ mask)
{
    extern __shared__ uint32_t smu[];
    uint32_t* Ks = smu;                       // [64][132] raw fp32 bits
    uint32_t* Vs = smu + ST_U32;              // [64][132]
    uint32_t* Ps = smu + 2 * ST_U32;          // [64][68] tf32 bits
    int* needb = (int*)(Ps + 64 * AP_STR);

    const int bh = blockIdx.y;
    const int qt = (gridDim.x - 1) - blockIdx.x;   // heavy blocks first
    const int q0 = qt * 64;
    const int tid = threadIdx.x;
    const int w = tid >> 5, lane = tid & 31;
    const int g = lane >> 2, tg = lane & 3;
    const int r1 = 16 * w + g;                     // local rows r1, r1+8 (0..63)
    const int gq1 = q0 + r1, gq2 = gq1 + 8;

    const float* __restrict__ Qp = Qg + (size_t)bh * T_ * E_;
    const float* __restrict__ Kp = Kg + (size_t)bh * T_ * E_;
    const float* __restrict__ Vp = Vg + (size_t)bh * T_ * E_;

    const uint32_t k_base = smem_u32addr(Ks);
    const uint32_t v_base = smem_u32addr(Vs);

    // --- stage Q (64x128) through Ks area, convert + scale, pull frags
#pragma unroll
    for (int i = 0; i < 16; i++) {
        int f = tid + i * 128;                // 0..2047 float4 slots
        int row = f >> 5, c4 = f & 31;
        float4 v = *(const float4*)&Qp[(size_t)(q0 + row) * E_ + 4 * c4];
        uint32_t* d = Ks + row * AK_STR + 4 * c4;
        d[0] = f2tf32(v.x * S2_); d[1] = f2tf32(v.y * S2_);
        d[2] = f2tf32(v.z * S2_); d[3] = f2tf32(v.w * S2_);
    }
    __syncthreads();
    uint32_t qf[16][4];
#pragma unroll
    for (int ks = 0; ks < 16; ks++) {
        const uint32_t* qb = Ks + r1 * AK_STR + 8 * ks;
        qf[ks][0] = qb[tg];
        qf[ks][1] = qb[8 * AK_STR + tg];
        qf[ks][2] = qb[tg + 4];
        qf[ks][3] = qb[8 * AK_STR + tg + 4];
    }
    __syncthreads();   // done reading staging area before loads overwrite

    float o[16][4];
#pragma unroll
    for (int ni = 0; ni < 16; ni++)
#pragma unroll
        for (int c = 0; c < 4; c++) o[ni][c] = 0.f;

    float m1 = -INFINITY, m2 = -INFINITY, l1 = 0.f, l2 = 0.f;
    const int ntA = qt + 1;

    // prologue: K(0) then V(0), each its own group
#pragma unroll
    for (int i = 0; i < 16; i++) {
        int f = tid + i * 128;
        int row = f >> 5, c4 = f & 31;
        uint32_t off = (uint32_t)(row * AK_STR + 4 * c4) * 4;
        cpa16(k_base + off, Kp + (size_t)row * E_ + 4 * c4);
    }
    CPA_COMMIT();
#pragma unroll
    for (int i = 0; i < 16; i++) {
        int f = tid + i * 128;
        int row = f >> 5, c4 = f & 31;
        uint32_t off = (uint32_t)(row * AV_STR + 4 * c4) * 4;
        cpa16(v_base + off, Vp + (size_t)row * E_ + 4 * c4);
    }
    CPA_COMMIT();

    // loop invariant at top: in-flight groups (old->new) = {K(kt), V(kt)}
    for (int kt = 0; kt < ntA; kt++) {
        const int kt0 = kt * 64;

        CPA_WAIT1();           // K(kt) complete
        __syncthreads();

        // prefetch mask rows into regs (independent of K; overlaps S-mma)
        int2 ma[8], mb[8];
#pragma unroll
        for (int ni = 0; ni < 8; ni++) {
            int k1 = kt0 + 8 * ni + 2 * tg;
            ma[ni] = *(const int2*)&mask[(size_t)gq1 * T_ + k1];
            mb[ni] = *(const int2*)&mask[(size_t)gq2 * T_ + k1];
        }

        // S = Q K^T (all warps active: rows >= kt0 for all causal tiles)
        float sacc[8][4];
#pragma unroll
        for (int ni = 0; ni < 8; ni++)
#pragma unroll
            for (int c = 0; c < 4; c++) sacc[ni][c] = 0.f;
#pragma unroll
        for (int ks = 0; ks < 16; ks++) {
#pragma unroll
            for (int ni = 0; ni < 8; ni++) {
                const uint32_t* kb = Ks + (8 * ni + g) * AK_STR + 8 * ks;
                uint32_t b[2] = { f2tf32(__uint_as_float(kb[tg])),
                                  f2tf32(__uint_as_float(kb[tg + 4])) };
                mma_tf32(sacc[ni], qf[ks], b);
            }
        }
        // causal + external mask (mask==0 -> -1e9 overrides causal -inf)
#pragma unroll
        for (int ni = 0; ni < 8; ni++) {
            int k1 = kt0 + 8 * ni + 2 * tg;
            if (k1 > gq1)     sacc[ni][0] = -INFINITY;
            if (k1 + 1 > gq1) sacc[ni][1] = -INFINITY;
            if (k1 > gq2)     sacc[ni][2] = -INFINITY;
            if (k1 + 1 > gq2) sacc[ni][3] = -INFINITY;
            if (ma[ni].x == 0) sacc[ni][0] = -1e9f;
            if (ma[ni].y == 0) sacc[ni][1] = -1e9f;
            if (mb[ni].x == 0) sacc[ni][2] = -1e9f;
            if (mb[ni].y == 0) sacc[ni][3] = -1e9f;
        }
        __syncthreads();       // all K reads done -> K buffer free

        // refill K with tile kt+1 while softmax runs
        if (kt + 1 < ntA) {
            const int nk0 = (kt + 1) * 64;
#pragma unroll
            for (int i = 0; i < 16; i++) {
                int f = tid + i * 128;
                int row = f >> 5, c4 = f & 31;
                uint32_t off = (uint32_t)(row * AK_STR + 4 * c4) * 4;
                cpa16(k_base + off, Kp + (size_t)(nk0 + row) * E_ + 4 * c4);
            }
        }
        CPA_COMMIT();          // in-flight: {V(kt), K(kt+1)}

        attn_softmax(sacc, m1, m2, l1, l2, o, Ps, r1, tg);

        CPA_WAIT1();           // V(kt) complete
        __syncthreads();

        attn_pv(o, Ps, Vs, r1, g, tg);
        __syncthreads();       // all V reads done -> V buffer free

        if (kt + 1 < ntA) {
            const int nk0 = (kt + 1) * 64;
#pragma unroll
            for (int i = 0; i < 16; i++) {
                int f = tid + i * 128;
                int row = f >> 5, c4 = f & 31;
                uint32_t off = (uint32_t)(row * AV_STR + 4 * c4) * 4;
                cpa16(v_base + off, Vp + (size_t)(nk0 + row) * E_ + 4 * c4);
            }
        }
        CPA_COMMIT();          // in-flight: {K(kt+1), V(kt+1)}
    }

    // Phase B: fully-masked rows attend to future mask==0 positions
    CPA_WAIT0();
    if (tid == 0) *needb = 0;
    __syncthreads();
    if ((m1 < -1e8f) || (m2 < -1e8f)) *needb = 1;
    __syncthreads();
    if (*needb) {
        for (int kt = ntA; kt < T_ / 64; kt++) {
            const int kt0 = kt * 64;
#pragma unroll
            for (int i = 0; i < 16; i++) {
                int f = tid + i * 128;
                int row = f >> 5, c4 = f & 31;
                uint32_t off = (uint32_t)(row * AV_STR + 4 * c4) * 4;
                cpa16(v_base + off, Vp + (size_t)(kt0 + row) * E_ + 4 * c4);
            }
            CPA_COMMIT();
            CPA_WAIT0();
            __syncthreads();
            unsigned anyd = __any_sync(0xffffffffu, (m1 < -1e8f) || (m2 < -1e8f));
            if (anyd) {
                float sacc[8][4];
#pragma unroll
                for (int ni = 0; ni < 8; ni++) {
                    int k1 = kt0 + 8 * ni + 2 * tg;
                    int2 mja = *(const int2*)&mask[(size_t)gq1 * T_ + k1];
                    int2 mjb = *(const int2*)&mask[(size_t)gq2 * T_ + k1];
                    sacc[ni][0] = mja.x ? -INFINITY : -1e9f;
                    sacc[ni][1] = mja.y ? -INFINITY : -1e9f;
                    sacc[ni][2] = mjb.x ? -INFINITY : -1e9f;
                    sacc[ni][3] = mjb.y ? -INFINITY : -1e9f;
                }
                attn_softmax(sacc, m1, m2, l1, l2, o, Ps, r1, tg);
                attn_pv(o, Ps, Vs, r1, g, tg);
            }
            __syncthreads();
        }
    }

    // epilogue: normalize and write Og[b*t][h*e]
    float inv1 = 1.f / l1, inv2 = 1.f / l2;
    const int b = bh >> 3, h = bh & 7;
    size_t base1 = ((size_t)(b * T_ + gq1)) * EH_ + h * E_;
    size_t base2 = base1 + (size_t)8 * EH_;
#pragma unroll
    for (int ni = 0; ni < 16; ni++) {
        int col = 8 * ni + 2 * tg;
        *(float2*)&Og[base1 + col] = make_float2(o[ni][0] * inv1, o[ni][1] * inv1);
        *(float2*)&Og[base2 + col] = make_float2(o[ni][2] * inv2, o[ni][3] * inv2);
    }
}

// ---------------------------------------------------------------------------
extern "C" void kernel_launch(void* const* d_in, const int* in_sizes, int n_in,
                              void* d_out, int out_size)
{
    const float* x   = (const float*)d_in[0];
    const int*  mask = (const int*)  d_in[1];
    const float* Wq  = (const float*)d_in[2];
    const float* Wk  = (const float*)d_in[3];
    const float* Wv  = (const float*)d_in[4];
    const float* Wu  = (const float*)d_in[5];
    const float* bu  = (const float*)d_in[6];
    float* out = (float*)d_out;

    cudaFuncSetAttribute(attn_kernel,
                         cudaFuncAttributeMaxDynamicSharedMemorySize, SMEM_ATTN);
    cudaFuncSetAttribute(qkv_mma_kernel,
                         cudaFuncAttributeMaxDynamicSharedMemorySize, SMEM_GEMM);
    cudaFuncSetAttribute(out_mma_kernel,
                         cudaFuncAttributeMaxDynamicSharedMemorySize, SMEM_OUT);

    qkv_mma_kernel<<<dim3(M_ / 128, H_, 3), 256, SMEM_GEMM>>>(x, Wq, Wk, Wv);
    attn_kernel<<<dim3(T_ / 64, BH_), 128, SMEM_ATTN>>>(mask);
    out_mma_kernel<<<dim3(M_ / 64, 1, 1), 256, SMEM_OUT>>>(Wu, bu, out);
}

// round 15
// speedup vs baseline: 1.8790x; 1.7710x over previous
#include <cuda_runtime.h>
#include <cuda_fp16.h>
#include <math.h>
#include <stdint.h>

#define B_  4
#define T_  2048
#define E_  128
#define H_  8
#define BH_ 32
#define M_  8192      // B*T
#define EH_ 1024      // E*H

// total softmax scale: e^-0.5 (folded into Qh at projection)
#define S2_ 0.08838834764831845f

// Projection GEMM smem (floats)
#define GA_STR 36
#define GB_STR 136
#define G_AS_FLOATS (128 * GA_STR)
#define G_BS_FLOATS (32 * GB_STR)
#define SMEM_GEMM ((G_AS_FLOATS + G_BS_FLOATS) * 4)     // 35840 B (>= 34816 B V-transpose stage)

#define G_AS2_FLOATS (64 * GA_STR)
#define SMEM_OUT ((G_AS2_FLOATS + G_BS_FLOATS) * 4)     // out kernel (M-tile 64)

// Attention smem (all fp16 payloads, u32 units)
#define AKH 68    // K tile row stride: 64 u32 data + pad  [64 t][128 e fp16]
#define AVH 36    // V^T tile row stride: 32 u32 + pad     [128 e][64 t fp16]
#define APH 36    // P row stride: 32 u32 + pad            [64 q][64 t fp16]
#define K_TILE_U32 (64 * AKH)
#define V_TILE_U32 (128 * AVH)
#define P_TILE_U32 (64 * APH)
#define SMEM_ATTN ((K_TILE_U32 + V_TILE_U32 + P_TILE_U32 + 4) * 4)   // ~45KB

// Scratch (device globals: allowed; runtime alloc is not)
__device__ __half Qh[(size_t)BH_ * T_ * E_];   // [bh][t][e], pre-scaled by S2_
__device__ __half Kh[(size_t)BH_ * T_ * E_];   // [bh][t][e]
__device__ __half Vt[(size_t)BH_ * E_ * T_];   // TRANSPOSED [bh][e][t]
__device__ float  Og[(size_t)M_ * EH_];        // [b*t][h*e]

// ---------------------------------------------------------------------------
// helpers (sm_80+ only; toolchain compiles at compute_100 non-a)
// ---------------------------------------------------------------------------
__device__ __forceinline__ uint32_t f2tf32(float f) {
    uint32_t r;
    asm("cvt.rna.tf32.f32 %0, %1;" : "=r"(r) : "f"(f));
    return r;
}
__device__ __forceinline__ uint32_t f22h2(float lo, float hi) {
    __half2 h = __floats2half2_rn(lo, hi);
    return *reinterpret_cast<uint32_t*>(&h);
}
__device__ __forceinline__ void mma_tf32(float* d, const uint32_t* a, const uint32_t* b) {
    asm volatile(
        "mma.sync.aligned.m16n8k8.row.col.f32.tf32.tf32.f32 "
        "{%0,%1,%2,%3}, {%4,%5,%6,%7}, {%8,%9}, {%0,%1,%2,%3};"
        : "+f"(d[0]), "+f"(d[1]), "+f"(d[2]), "+f"(d[3])
        : "r"(a[0]), "r"(a[1]), "r"(a[2]), "r"(a[3]), "r"(b[0]), "r"(b[1]));
}
__device__ __forceinline__ void mma_f16(float* d, const uint32_t* a, const uint32_t* b) {
    asm volatile(
        "mma.sync.aligned.m16n8k16.row.col.f32.f16.f16.f32 "
        "{%0,%1,%2,%3}, {%4,%5,%6,%7}, {%8,%9}, {%0,%1,%2,%3};"
        : "+f"(d[0]), "+f"(d[1]), "+f"(d[2]), "+f"(d[3])
        : "r"(a[0]), "r"(a[1]), "r"(a[2]), "r"(a[3]), "r"(b[0]), "r"(b[1]));
}
__device__ __forceinline__ uint32_t smem_u32addr(const void* p) {
    uint32_t a;
    asm("{ .reg .u64 t; cvta.to.shared.u64 t, %1; cvt.u32.u64 %0, t; }"
        : "=r"(a) : "l"(p));
    return a;
}
__device__ __forceinline__ void cpa16(uint32_t s, const void* g) {
    asm volatile("cp.async.cg.shared.global [%0], [%1], 16;" :: "r"(s), "l"(g));
}
#define CPA_COMMIT() asm volatile("cp.async.commit_group;" ::: "memory")
#define CPA_WAIT1()  asm volatile("cp.async.wait_group 1;" ::: "memory")
#define CPA_WAIT0()  asm volatile("cp.async.wait_group 0;" ::: "memory")

// ---------------------------------------------------------------------------
// Kernel 1: QKV projection via tf32 mma.sync; fp16 outputs.
// Q (scaled) and K written [bh][t][e]; V written TRANSPOSED [bh][e][t].
// ---------------------------------------------------------------------------
__global__ __launch_bounds__(256) void qkv_mma_kernel(
    const float* __restrict__ x,
    const float* __restrict__ Wq,
    const float* __restrict__ Wk,
    const float* __restrict__ Wv)
{
    extern __shared__ float sm[];
    uint32_t* AsU = (uint32_t*)sm;
    uint32_t* BsU = (uint32_t*)(sm + G_AS_FLOATS);

    const int z  = blockIdx.z;
    const float* __restrict__ Wp = (z == 0) ? Wq : (z == 1) ? Wk : Wv;
    const int m0 = blockIdx.x * 128;
    const int h  = blockIdx.y;
    const int n0 = h * 128;

    const int tid  = threadIdx.x;
    const int warp = tid >> 5, lane = tid & 31;
    const int g = lane >> 2, tg = lane & 3;
    const int wm0 = (warp & 1) * 64;
    const int wn0 = (warp >> 1) * 32;

    float acc[4][4][4];
#pragma unroll
    for (int mi = 0; mi < 4; mi++)
#pragma unroll
        for (int ni = 0; ni < 4; ni++)
#pragma unroll
            for (int c = 0; c < 4; c++) acc[mi][ni][c] = 0.f;

    for (int kc = 0; kc < 4; kc++) {
        const int k0 = kc * 32;
#pragma unroll
        for (int i = 0; i < 4; i++) {
            int f = tid + i * 256;
            int row = f >> 3, s4 = f & 7;
            float4 v = *(const float4*)&x[(size_t)(m0 + row) * E_ + k0 + 4 * s4];
            AsU[row * GA_STR + 4 * s4 + 0] = f2tf32(v.x);
            AsU[row * GA_STR + 4 * s4 + 1] = f2tf32(v.y);
            AsU[row * GA_STR + 4 * s4 + 2] = f2tf32(v.z);
            AsU[row * GA_STR + 4 * s4 + 3] = f2tf32(v.w);
        }
#pragma unroll
        for (int i = 0; i < 4; i++) {
            int f = tid + i * 256;
            int kk = f >> 5, n4 = f & 31;
            float4 v = *(const float4*)&Wp[(size_t)(k0 + kk) * EH_ + n0 + 4 * n4];
            BsU[kk * GB_STR + 4 * n4 + 0] = f2tf32(v.x);
            BsU[kk * GB_STR + 4 * n4 + 1] = f2tf32(v.y);
            BsU[kk * GB_STR + 4 * n4 + 2] = f2tf32(v.z);
            BsU[kk * GB_STR + 4 * n4 + 3] = f2tf32(v.w);
        }
        __syncthreads();

#pragma unroll
        for (int ks = 0; ks < 4; ks++) {
            const int kb = 8 * ks;
            uint32_t a[4][4], b[4][2];
#pragma unroll
            for (int mi = 0; mi < 4; mi++) {
                int r = wm0 + 16 * mi + g;
                a[mi][0] = AsU[r * GA_STR + kb + tg];
                a[mi][1] = AsU[(r + 8) * GA_STR + kb + tg];
                a[mi][2] = AsU[r * GA_STR + kb + tg + 4];
                a[mi][3] = AsU[(r + 8) * GA_STR + kb + tg + 4];
            }
#pragma unroll
            for (int ni = 0; ni < 4; ni++) {
                int col = wn0 + 8 * ni + g;
                b[ni][0] = BsU[(kb + tg) * GB_STR + col];
                b[ni][1] = BsU[(kb + tg + 4) * GB_STR + col];
            }
#pragma unroll
            for (int mi = 0; mi < 4; mi++)
#pragma unroll
                for (int ni = 0; ni < 4; ni++)
                    mma_tf32(acc[mi][ni], a[mi], b[ni]);
        }
        __syncthreads();
    }

    const int b_ = m0 >> 11;
    const int t0 = m0 & 2047;

    if (z == 2) {
        // V: transpose via smem stage [128 e][136 halfs] (34816 B), then
        // write Vt[bh][e][t] coalesced along t.
        __half* Ts = (__half*)sm;
#pragma unroll
        for (int mi = 0; mi < 4; mi++) {
            int rl = wm0 + 16 * mi + g;
#pragma unroll
            for (int ni = 0; ni < 4; ni++) {
                int cb = wn0 + 8 * ni + 2 * tg;
                Ts[cb * 136 + rl]           = __float2half_rn(acc[mi][ni][0]);
                Ts[(cb + 1) * 136 + rl]     = __float2half_rn(acc[mi][ni][1]);
                Ts[cb * 136 + rl + 8]       = __float2half_rn(acc[mi][ni][2]);
                Ts[(cb + 1) * 136 + rl + 8] = __float2half_rn(acc[mi][ni][3]);
            }
        }
        __syncthreads();
        const uint32_t* Tu = (const uint32_t*)sm;   // stride 68 u32 per e row
        uint32_t* Vu = (uint32_t*)Vt;
#pragma unroll
        for (int i = 0; i < 32; i++) {
            int f = tid + i * 256;              // 0..8191 u32
            int e = f >> 6, c = f & 63;         // 128 e x 64 u32 (128 t halfs)
            uint32_t v = Tu[e * 68 + c];
            size_t dst = ((((size_t)(b_ * H_ + h) * E_ + e) * T_ + t0) >> 1) + c;
            Vu[dst] = v;
        }
    } else {
        uint32_t* outu = (uint32_t*)((z == 0) ? Qh : Kh);
        const float sc = (z == 0) ? S2_ : 1.f;
#pragma unroll
        for (int mi = 0; mi < 4; mi++) {
            int rl = wm0 + 16 * mi + g;
            size_t r0u = ((size_t)(b_ * H_ + h) * T_ + t0 + rl) * (E_ / 2);
#pragma unroll
            for (int ni = 0; ni < 4; ni++) {
                int nu = (wn0 >> 1) + 4 * ni + tg;    // u32 col index
                outu[r0u + nu] =
                    f22h2(acc[mi][ni][0] * sc, acc[mi][ni][1] * sc);
                // FIXED: +8 rows = 8*(E_/2) u32 (was 4*(E_/2) -> +4 rows)
                outu[r0u + 8 * (E_ / 2) + nu] =
                    f22h2(acc[mi][ni][2] * sc, acc[mi][ni][3] * sc);
            }
        }
    }
}

// ---------------------------------------------------------------------------
// Kernel 3: output projection, tf32, M-tile 64 (unchanged, measured good).
// ---------------------------------------------------------------------------
__global__ __launch_bounds__(256) void out_mma_kernel(
    const float* __restrict__ Wu,
    const float* __restrict__ bu,
    float* __restrict__ out)
{
    extern __shared__ float sm[];
    uint32_t* AsU = (uint32_t*)sm;                   // [64][36]
    uint32_t* BsU = (uint32_t*)(sm + G_AS2_FLOATS);  // [32][136]

    const int m0 = blockIdx.x * 64;
    const int tid  = threadIdx.x;
    const int warp = tid >> 5, lane = tid & 31;
    const int g = lane >> 2, tg = lane & 3;
    const int wm0 = (warp & 1) * 32;
    const int wn0 = (warp >> 1) * 32;

    float acc[2][4][4];
#pragma unroll
    for (int mi = 0; mi < 2; mi++)
#pragma unroll
        for (int ni = 0; ni < 4; ni++)
#pragma unroll
            for (int c = 0; c < 4; c++) acc[mi][ni][c] = 0.f;

    for (int kc = 0; kc < 32; kc++) {
        const int k0 = kc * 32;
#pragma unroll
        for (int i = 0; i < 2; i++) {
            int f = tid + i * 256;
            int row = f >> 3, s4 = f & 7;
            float4 v = *(const float4*)&Og[(size_t)(m0 + row) * EH_ + k0 + 4 * s4];
            AsU[row * GA_STR + 4 * s4 + 0] = f2tf32(v.x);
            AsU[row * GA_STR + 4 * s4 + 1] = f2tf32(v.y);
            AsU[row * GA_STR + 4 * s4 + 2] = f2tf32(v.z);
            AsU[row * GA_STR + 4 * s4 + 3] = f2tf32(v.w);
        }
#pragma unroll
        for (int i = 0; i < 4; i++) {
            int f = tid + i * 256;
            int kk = f >> 5, n4 = f & 31;
            float4 v = *(const float4*)&Wu[(size_t)(k0 + kk) * E_ + 4 * n4];
            BsU[kk * GB_STR + 4 * n4 + 0] = f2tf32(v.x);
            BsU[kk * GB_STR + 4 * n4 + 1] = f2tf32(v.y);
            BsU[kk * GB_STR + 4 * n4 + 2] = f2tf32(v.z);
            BsU[kk * GB_STR + 4 * n4 + 3] = f2tf32(v.w);
        }
        __syncthreads();

#pragma unroll
        for (int ks = 0; ks < 4; ks++) {
            const int kb = 8 * ks;
            uint32_t a[2][4], b[4][2];
#pragma unroll
            for (int mi = 0; mi < 2; mi++) {
                int r = wm0 + 16 * mi + g;
                a[mi][0] = AsU[r * GA_STR + kb + tg];
                a[mi][1] = AsU[(r + 8) * GA_STR + kb + tg];
                a[mi][2] = AsU[r * GA_STR + kb + tg + 4];
                a[mi][3] = AsU[(r + 8) * GA_STR + kb + tg + 4];
            }
#pragma unroll
            for (int ni = 0; ni < 4; ni++) {
                int col = wn0 + 8 * ni + g;
                b[ni][0] = BsU[(kb + tg) * GB_STR + col];
                b[ni][1] = BsU[(kb + tg + 4) * GB_STR + col];
            }
#pragma unroll
            for (int mi = 0; mi < 2; mi++)
#pragma unroll
                for (int ni = 0; ni < 4; ni++)
                    mma_tf32(acc[mi][ni], a[mi], b[ni]);
        }
        __syncthreads();
    }

#pragma unroll
    for (int mi = 0; mi < 2; mi++) {
        int m = m0 + wm0 + 16 * mi + g;
#pragma unroll
        for (int ni = 0; ni < 4; ni++) {
            int n = wn0 + 8 * ni + 2 * tg;
            float2 bias = *(const float2*)&bu[n];
            *(float2*)&out[(size_t)m * E_ + n] =
                make_float2(acc[mi][ni][0] + bias.x, acc[mi][ni][1] + bias.y);
            *(float2*)&out[(size_t)(m + 8) * E_ + n] =
                make_float2(acc[mi][ni][2] + bias.x, acc[mi][ni][3] + bias.y);
        }
    }
}

// ---------------------------------------------------------------------------
// Attention softmax: updates m/l, scales o, writes P as half2 to smem.
// ---------------------------------------------------------------------------
__device__ __forceinline__ void attn_softmax(
    float sacc[8][4], float& m1, float& m2, float& l1, float& l2,
    float o[16][4], uint32_t* Ps, int r1, int tg)
{
    float mt1 = -INFINITY, mt2 = -INFINITY;
#pragma unroll
    for (int ni = 0; ni < 8; ni++) {
        mt1 = fmaxf(mt1, fmaxf(sacc[ni][0], sacc[ni][1]));
        mt2 = fmaxf(mt2, fmaxf(sacc[ni][2], sacc[ni][3]));
    }
    mt1 = fmaxf(mt1, __shfl_xor_sync(0xffffffffu, mt1, 1));
    mt1 = fmaxf(mt1, __shfl_xor_sync(0xffffffffu, mt1, 2));
    mt2 = fmaxf(mt2, __shfl_xor_sync(0xffffffffu, mt2, 1));
    mt2 = fmaxf(mt2, __shfl_xor_sync(0xffffffffu, mt2, 2));
    float mn1 = fmaxf(m1, mt1), mn2 = fmaxf(m2, mt2);
    float al1 = (m1 == mn1) ? 1.f : __expf(m1 - mn1);
    float al2 = (m2 == mn2) ? 1.f : __expf(m2 - mn2);
    float me1 = (mn1 == -INFINITY) ? 0.f : mn1;
    float me2 = (mn2 == -INFINITY) ? 0.f : mn2;
    float ls1 = 0.f, ls2 = 0.f;
#pragma unroll
    for (int ni = 0; ni < 8; ni++) {
        float p0 = __expf(sacc[ni][0] - me1);
        float p1 = __expf(sacc[ni][1] - me1);
        float p2 = __expf(sacc[ni][2] - me2);
        float p3 = __expf(sacc[ni][3] - me2);
        ls1 += p0 + p1; ls2 += p2 + p3;
        Ps[r1 * APH + 4 * ni + tg]       = f22h2(p0, p1);
        Ps[(r1 + 8) * APH + 4 * ni + tg] = f22h2(p2, p3);
    }
    ls1 += __shfl_xor_sync(0xffffffffu, ls1, 1);
    ls1 += __shfl_xor_sync(0xffffffffu, ls1, 2);
    ls2 += __shfl_xor_sync(0xffffffffu, ls2, 1);
    ls2 += __shfl_xor_sync(0xffffffffu, ls2, 2);
    l1 = l1 * al1 + ls1; m1 = mn1;
    l2 = l2 * al2 + ls2; m2 = mn2;
#pragma unroll
    for (int ni = 0; ni < 16; ni++) {
        o[ni][0] *= al1; o[ni][1] *= al1;
        o[ni][2] *= al2; o[ni][3] *= al2;
    }
    __syncwarp();   // Ps writes visible warp-wide before PV frag loads
}

// PV: O += P @ V (fp16 mma, V^T in smem -> contiguous half2 frags).
__device__ __forceinline__ void attn_pv(
    float o[16][4], const uint32_t* Ps, const uint32_t* Vs, int r1, int g, int tg)
{
#pragma unroll
    for (int kp = 0; kp < 4; kp++) {
        uint32_t a[4];
        a[0] = Ps[r1 * APH + kp * 8 + tg];
        a[1] = Ps[(r1 + 8) * APH + kp * 8 + tg];
        a[2] = Ps[r1 * APH + kp * 8 + 4 + tg];
        a[3] = Ps[(r1 + 8) * APH + kp * 8 + 4 + tg];
#pragma unroll
        for (int ni = 0; ni < 16; ni++) {
            const uint32_t* vb = Vs + (8 * ni + g) * AVH + kp * 8;
            uint32_t b[2] = { vb[tg], vb[tg + 4] };
            mma_f16(o[ni], a, b);
        }
    }
    __syncwarp();   // all lanes done reading Ps before next tile overwrites
}

// ---------------------------------------------------------------------------
// Kernel 2: flash attention, all-fp16 operands, m16n8k16. BM=64, 128 threads,
// 2 CTAs/SM, staggered K/V pipeline (R12 structure).
// ---------------------------------------------------------------------------
__global__ __launch_bounds__(128, 2) void attn_kernel(const int* __restrict__ mask)
{
    extern __shared__ uint32_t smu[];
    uint32_t* Ks = smu;                       // [64][AKH]  K tile (fp16 pairs)
    uint32_t* Vs = smu + K_TILE_U32;          // [128][AVH] V^T tile
    uint32_t* Ps = Vs + V_TILE_U32;           // [64][APH]  P (half2)
    int* needb = (int*)(Ps + P_TILE_U32);

    const int bh = blockIdx.y;
    const int qt = (gridDim.x - 1) - blockIdx.x;   // heavy blocks first
    const int q0 = qt * 64;
    const int tid = threadIdx.x;
    const int w = tid >> 5, lane = tid & 31;
    const int g = lane >> 2, tg = lane & 3;
    const int r1 = 16 * w + g;                     // local rows r1, r1+8 (0..63)
    const int gq1 = q0 + r1, gq2 = gq1 + 8;

    const __half* __restrict__ Qp = Qh + (size_t)bh * T_ * E_;
    const __half* __restrict__ Kp = Kh + (size_t)bh * T_ * E_;
    const __half* __restrict__ Vp = Vt + (size_t)bh * E_ * T_;

    const uint32_t k_base = smem_u32addr(Ks);
    const uint32_t v_base = smem_u32addr(Vs);

    // --- stage Q (64x128 fp16) through Ks area, pull frags to regs
#pragma unroll
    for (int i = 0; i < 8; i++) {
        int f = tid + i * 128;                // 0..1023 (16B chunks)
        int row = f >> 4, c = f & 15;
        uint4 v = *(const uint4*)&Qp[(size_t)(q0 + row) * E_ + 8 * c];
        *(uint4*)&Ks[row * AKH + 4 * c] = v;
    }
    __syncthreads();
    uint32_t qf[8][4];
#pragma unroll
    for (int ks = 0; ks < 8; ks++) {
        const uint32_t* qb = Ks + r1 * AKH + 8 * ks;
        qf[ks][0] = qb[tg];
        qf[ks][1] = qb[8 * AKH + tg];
        qf[ks][2] = qb[tg + 4];
        qf[ks][3] = qb[8 * AKH + tg + 4];
    }
    __syncthreads();   // done reading staging area before loads overwrite

    float o[16][4];
#pragma unroll
    for (int ni = 0; ni < 16; ni++)
#pragma unroll
        for (int c = 0; c < 4; c++) o[ni][c] = 0.f;

    float m1 = -INFINITY, m2 = -INFINITY, l1 = 0.f, l2 = 0.f;
    const int ntA = qt + 1;

    // prologue: K(0) then V(0), each its own cp.async group
#pragma unroll
    for (int i = 0; i < 8; i++) {
        int f = tid + i * 128;
        int row = f >> 4, c = f & 15;
        cpa16(k_base + (uint32_t)(row * AKH + 4 * c) * 4,
              Kp + (size_t)row * E_ + 8 * c);
    }
    CPA_COMMIT();
#pragma unroll
    for (int i = 0; i < 8; i++) {
        int f = tid + i * 128;
        int row = f >> 3, c = f & 7;          // 128 e-rows x 8 chunks
        cpa16(v_base + (uint32_t)(row * AVH + 4 * c) * 4,
              Vp + (size_t)row * T_ + 8 * c);
    }
    CPA_COMMIT();

    // loop invariant at top: in-flight groups (old->new) = {K(kt), V(kt)}
    for (int kt = 0; kt < ntA; kt++) {
        const int kt0 = kt * 64;

        CPA_WAIT1();           // K(kt) complete
        __syncthreads();

        // prefetch mask rows into regs (independent of K; overlaps S-mma)
        int2 ma[8], mb[8];
#pragma unroll
        for (int ni = 0; ni < 8; ni++) {
            int k1 = kt0 + 8 * ni + 2 * tg;
            ma[ni] = *(const int2*)&mask[(size_t)gq1 * T_ + k1];
            mb[ni] = *(const int2*)&mask[(size_t)gq2 * T_ + k1];
        }

        // S = Q K^T  (fp16 k16: 8 ks x 8 ni)
        float sacc[8][4];
#pragma unroll
        for (int ni = 0; ni < 8; ni++)
#pragma unroll
            for (int c = 0; c < 4; c++) sacc[ni][c] = 0.f;
#pragma unroll
        for (int ks = 0; ks < 8; ks++) {
#pragma unroll
            for (int ni = 0; ni < 8; ni++) {
                const uint32_t* kb = Ks + (8 * ni + g) * AKH + 8 * ks;
                uint32_t b[2] = { kb[tg], kb[tg + 4] };
                mma_f16(sacc[ni], qf[ks], b);
            }
        }
        // causal + external mask (mask==0 -> -1e9 overrides causal -inf)
#pragma unroll
        for (int ni = 0; ni < 8; ni++) {
            int k1 = kt0 + 8 * ni + 2 * tg;
            if (k1 > gq1)     sacc[ni][0] = -INFINITY;
            if (k1 + 1 > gq1) sacc[ni][1] = -INFINITY;
            if (k1 > gq2)     sacc[ni][2] = -INFINITY;
            if (k1 + 1 > gq2) sacc[ni][3] = -INFINITY;
            if (ma[ni].x == 0) sacc[ni][0] = -1e9f;
            if (ma[ni].y == 0) sacc[ni][1] = -1e9f;
            if (mb[ni].x == 0) sacc[ni][2] = -1e9f;
            if (mb[ni].y == 0) sacc[ni][3] = -1e9f;
        }
        __syncthreads();       // all K reads done -> K buffer free

        // refill K with tile kt+1 while softmax runs
        if (kt + 1 < ntA) {
            const int nk0 = (kt + 1) * 64;
#pragma unroll
            for (int i = 0; i < 8; i++) {
                int f = tid + i * 128;
                int row = f >> 4, c = f & 15;
                cpa16(k_base + (uint32_t)(row * AKH + 4 * c) * 4,
                      Kp + (size_t)(nk0 + row) * E_ + 8 * c);
            }
        }
        CPA_COMMIT();          // in-flight: {V(kt), K(kt+1)}

        attn_softmax(sacc, m1, m2, l1, l2, o, Ps, r1, tg);

        CPA_WAIT1();           // V(kt) complete
        __syncthreads();

        attn_pv(o, Ps, Vs, r1, g, tg);
        __syncthreads();       // all V reads done -> V buffer free

        if (kt + 1 < ntA) {
            const int nk0 = (kt + 1) * 64;
#pragma unroll
            for (int i = 0; i < 8; i++) {
                int f = tid + i * 128;
                int row = f >> 3, c = f & 7;
                cpa16(v_base + (uint32_t)(row * AVH + 4 * c) * 4,
                      Vp + (size_t)row * T_ + nk0 + 8 * c);
            }
        }
        CPA_COMMIT();          // in-flight: {K(kt+1), V(kt+1)}
    }

    // Phase B: fully-masked rows attend to future mask==0 positions
    CPA_WAIT0();
    if (tid == 0) *needb = 0;
    __syncthreads();
    if ((m1 < -1e8f) || (m2 < -1e8f)) *needb = 1;
    __syncthreads();
    if (*needb) {
        for (int kt = ntA; kt < T_ / 64; kt++) {
            const int kt0 = kt * 64;
#pragma unroll
            for (int i = 0; i < 8; i++) {
                int f = tid + i * 128;
                int row = f >> 3, c = f & 7;
                cpa16(v_base + (uint32_t)(row * AVH + 4 * c) * 4,
                      Vp + (size_t)row * T_ + kt0 + 8 * c);
            }
            CPA_COMMIT();
            CPA_WAIT0();
            __syncthreads();
            unsigned anyd = __any_sync(0xffffffffu, (m1 < -1e8f) || (m2 < -1e8f));
            if (anyd) {
                float sacc[8][4];
#pragma unroll
                for (int ni = 0; ni < 8; ni++) {
                    int k1 = kt0 + 8 * ni + 2 * tg;
                    int2 mja = *(const int2*)&mask[(size_t)gq1 * T_ + k1];
                    int2 mjb = *(const int2*)&mask[(size_t)gq2 * T_ + k1];
                    sacc[ni][0] = mja.x ? -INFINITY : -1e9f;
                    sacc[ni][1] = mja.y ? -INFINITY : -1e9f;
                    sacc[ni][2] = mjb.x ? -INFINITY : -1e9f;
                    sacc[ni][3] = mjb.y ? -INFINITY : -1e9f;
                }
                attn_softmax(sacc, m1, m2, l1, l2, o, Ps, r1, tg);
                attn_pv(o, Ps, Vs, r1, g, tg);
            }
            __syncthreads();
        }
    }

    // epilogue: normalize and write Og[b*t][h*e]
    float inv1 = 1.f / l1, inv2 = 1.f / l2;
    const int b = bh >> 3, h = bh & 7;
    size_t base1 = ((size_t)(b * T_ + gq1)) * EH_ + h * E_;
    size_t base2 = base1 + (size_t)8 * EH_;
#pragma unroll
    for (int ni = 0; ni < 16; ni++) {
        int col = 8 * ni + 2 * tg;
        *(float2*)&Og[base1 + col] = make_float2(o[ni][0] * inv1, o[ni][1] * inv1);
        *(float2*)&Og[base2 + col] = make_float2(o[ni][2] * inv2, o[ni][3] * inv2);
    }
}

// ---------------------------------------------------------------------------
extern "C" void kernel_launch(void* const* d_in, const int* in_sizes, int n_in,
                              void* d_out, int out_size)
{
    const float* x   = (const float*)d_in[0];
    const int*  mask = (const int*)  d_in[1];
    const float* Wq  = (const float*)d_in[2];
    const float* Wk  = (const float*)d_in[3];
    const float* Wv  = (const float*)d_in[4];
    const float* Wu  = (const float*)d_in[5];
    const float* bu  = (const float*)d_in[6];
    float* out = (float*)d_out;

    cudaFuncSetAttribute(attn_kernel,
                         cudaFuncAttributeMaxDynamicSharedMemorySize, SMEM_ATTN);
    cudaFuncSetAttribute(qkv_mma_kernel,
                         cudaFuncAttributeMaxDynamicSharedMemorySize, SMEM_GEMM);
    cudaFuncSetAttribute(out_mma_kernel,
                         cudaFuncAttributeMaxDynamicSharedMemorySize, SMEM_OUT);

    qkv_mma_kernel<<<dim3(M_ / 128, H_, 3), 256, SMEM_GEMM>>>(x, Wq, Wk, Wv);
    attn_kernel<<<dim3(T_ / 64, BH_), 128, SMEM_ATTN>>>(mask);
    out_mma_kernel<<<dim3(M_ / 64, 1, 1), 256, SMEM_OUT>>>(Wu, bu, out);
}